// round 8
// baseline (speedup 1.0000x reference)
#include <cuda_runtime.h>
#include <cuda_fp16.h>
#include <cstdint>
#include <math.h>

#define EMBED  1024
#define HIDDEN 512
#define NB     4
#define SQ     4096
#define SKV    4096
#define MTOK   (NB * SQ)   // 16384

typedef __half  f16;
typedef __half2 f162;

// ---------------- scratch (static device arrays; no allocations) ----------------
__device__ f16  g_qfh [(size_t)MTOK * EMBED];        // fp16 q_feat
__device__ f16  g_kvh [(size_t)MTOK * EMBED];        // fp16 kv_feat
__device__ f16  g_Qh  [(size_t)MTOK * HIDDEN];       // fp16 Q
__device__ f16  g_Kh  [(size_t)MTOK * HIDDEN];       // fp16 K
__device__ int8_t g_Qi [(size_t)MTOK * HIDDEN];      // int8 Q
__device__ int8_t g_Ki [(size_t)MTOK * HIDDEN];      // int8 K
__device__ float g_sQ [MTOK];                        // Q row scales
__device__ float g_sK [MTOK];                        // K row scales
__device__ f16  g_VT  [(size_t)HIDDEN * MTOK];       // fp16 V^T [H, tokens]
__device__ f16  g_S   [(size_t)NB * SQ * SKV];       // unnormalized exp-scores
__device__ float g_Zi [MTOK];                        // 1/rowsum
__device__ f16  g_Ch  [(size_t)MTOK * HIDDEN];       // fp16 ctx
__device__ f16  g_O1h [(size_t)MTOK * EMBED];        // fp16 O1 (ctx@Wo+bo+qf)
__device__ float g_O2 [(size_t)MTOK * EMBED];        // fp32 pre-LN
__device__ f16  g_Wq1 [(size_t)HIDDEN * EMBED];      // fp16 Wq^T
__device__ f16  g_Wk1 [(size_t)HIDDEN * EMBED];
__device__ f16  g_Wv1 [(size_t)HIDDEN * EMBED];
__device__ f16  g_Wo1 [(size_t)EMBED * HIDDEN];      // fp16 Wo^T
__device__ f16  g_Wfc1[(size_t)EMBED * EMBED];       // fp16 Wfc^T

// ================= helpers =================
__device__ __forceinline__ uint32_t smem_u32(const void* p) {
    return (uint32_t)__cvta_generic_to_shared((void*)p);
}
#define SWZ128(o) ((o) ^ (((o) >> 3) & 0x70))

__device__ __forceinline__ void cpa16(uint32_t s, const void* g) {
    asm volatile("cp.async.cg.shared.global [%0], [%1], 16;" :: "r"(s), "l"(g));
}
__device__ __forceinline__ void cpa_commit() {
    asm volatile("cp.async.commit_group;" ::: "memory");
}
template <int N> __device__ __forceinline__ void cpa_wait() {
    asm volatile("cp.async.wait_group %0;" :: "n"(N) : "memory");
}
__device__ __forceinline__ void ldsm_x4(uint32_t a, uint32_t& r0, uint32_t& r1,
                                        uint32_t& r2, uint32_t& r3) {
    asm volatile("ldmatrix.sync.aligned.m8n8.x4.shared.b16 {%0,%1,%2,%3}, [%4];"
                 : "=r"(r0), "=r"(r1), "=r"(r2), "=r"(r3) : "r"(a));
}
__device__ __forceinline__ void mma16816(float* c, const uint32_t* a, const uint32_t* b) {
    asm volatile("mma.sync.aligned.m16n8k16.row.col.f32.f16.f16.f32 "
                 "{%0,%1,%2,%3}, {%4,%5,%6,%7}, {%8,%9}, {%0,%1,%2,%3};"
                 : "+f"(c[0]), "+f"(c[1]), "+f"(c[2]), "+f"(c[3])
                 : "r"(a[0]), "r"(a[1]), "r"(a[2]), "r"(a[3]), "r"(b[0]), "r"(b[1]));
}
__device__ __forceinline__ void imma16832(int* c, const uint32_t* a, const uint32_t* b) {
    asm volatile("mma.sync.aligned.m16n8k32.row.col.s32.s8.s8.s32 "
                 "{%0,%1,%2,%3}, {%4,%5,%6,%7}, {%8,%9}, {%0,%1,%2,%3};"
                 : "+r"(c[0]), "+r"(c[1]), "+r"(c[2]), "+r"(c[3])
                 : "r"(a[0]), "r"(a[1]), "r"(a[2]), "r"(a[3]), "r"(b[0]), "r"(b[1]));
}
__device__ __forceinline__ float ex2_mufu(float t) {
    float r;
    asm("ex2.approx.f32 %0, %1;" : "=f"(r) : "f"(t));
    return r;
}

// ================= fp16 NT GEMM (unchanged from R7) =================
#define STAGE_B 32768
#define GSMEM   (3 * STAGE_B)   // 98304

template <int MODE>
__global__ void __launch_bounds__(256, 2)
gemm_nt(const f16* __restrict__ Ag, const f16* __restrict__ Bg,
        void* __restrict__ Cg, int Kp, int lda, int ldb, int ldc,
        long long sA, long long sB, long long sC,
        const float* __restrict__ aux1, const float* __restrict__ aux2,
        long long sAux, float escale2)
{
    extern __shared__ char smc[];
    const uint32_t sm0 = smem_u32(smc);
    const int tid  = threadIdx.x;
    const int wid  = tid >> 5;
    const int lane = tid & 31;
    const int wm = wid >> 2;
    const int wn = wid & 3;
    const int m0 = blockIdx.y * 128;
    const int n0 = blockIdx.x * 128;

    Ag += (long long)blockIdx.z * sA;
    Bg += (long long)blockIdx.z * sB;

    const f16* Abase = Ag + (long long)m0 * lda;
    const f16* Bbase = Bg + (long long)n0 * ldb;

    const int crow = tid >> 3;
    const int ccol = tid & 7;

    float acc[4][4][4];
    #pragma unroll
    for (int a = 0; a < 4; a++)
        #pragma unroll
        for (int b = 0; b < 4; b++)
            #pragma unroll
            for (int c = 0; c < 4; c++) acc[a][b][c] = 0.0f;

    const int KT = Kp >> 6;

    auto load_stage = [&](int st, int kt) {
        const uint32_t sa = sm0 + st * STAGE_B;
        const uint32_t sb = sa + 16384;
        const int kofs = kt * 64;
        #pragma unroll
        for (int i = 0; i < 4; i++) {
            const int row = crow + i * 32;
            const uint32_t soff = SWZ128((uint32_t)(row * 128 + ccol * 16));
            cpa16(sa + soff, Abase + (long long)row * lda + kofs + ccol * 8);
            cpa16(sb + soff, Bbase + (long long)row * ldb + kofs + ccol * 8);
        }
    };

    load_stage(0, 0); cpa_commit();
    load_stage(1, 1); cpa_commit();

    int st = 0;
    for (int kt = 0; kt < KT; ++kt) {
        cpa_wait<1>();
        __syncthreads();

        const uint32_t sa = sm0 + st * STAGE_B;
        const uint32_t sb = sa + 16384;

        #pragma unroll
        for (int ks = 0; ks < 4; ks++) {
            uint32_t afr[4][4];
            uint32_t bfr[4][2];
            const int bcol = ks * 32 + ((lane >> 4) << 4);
            #pragma unroll
            for (int mt = 0; mt < 4; mt++) {
                const int row = wm * 64 + mt * 16 + (lane & 15);
                ldsm_x4(sa + SWZ128((uint32_t)(row * 128 + bcol)),
                        afr[mt][0], afr[mt][1], afr[mt][2], afr[mt][3]);
            }
            #pragma unroll
            for (int np = 0; np < 2; np++) {
                const int row = wn * 32 + np * 16 + (lane & 15);
                uint32_t r0, r1, r2, r3;
                ldsm_x4(sb + SWZ128((uint32_t)(row * 128 + bcol)), r0, r1, r2, r3);
                bfr[2*np][0] = r0;   bfr[2*np][1] = r2;
                bfr[2*np+1][0] = r1; bfr[2*np+1][1] = r3;
            }
            #pragma unroll
            for (int mt = 0; mt < 4; mt++)
                #pragma unroll
                for (int nt = 0; nt < 4; nt++)
                    mma16816(acc[mt][nt], afr[mt], bfr[nt]);
        }

        if (kt + 2 < KT) {
            int nst = st + 2; if (nst >= 3) nst -= 3;
            load_stage(nst, kt + 2);
        }
        cpa_commit();
        if (++st == 3) st = 0;
    }

    const float* rs = (MODE == 5) ? (aux1 + (long long)blockIdx.z * sAux) : nullptr;

    #pragma unroll
    for (int mt = 0; mt < 4; mt++) {
        const int r0 = m0 + wm * 64 + mt * 16 + (lane >> 2);
        const int r1 = r0 + 8;
        float rs0 = 1.0f, rs1 = 1.0f;
        if (MODE == 5) { rs0 = rs[r0]; rs1 = rs[r1]; }
        #pragma unroll
        for (int nt = 0; nt < 4; nt++) {
            const int c = n0 + wn * 32 + nt * 8 + (lane & 3) * 2;
            float x0 = acc[mt][nt][0], y0 = acc[mt][nt][1];
            float x1 = acc[mt][nt][2], y1 = acc[mt][nt][3];
            if (MODE == 5) { x0 *= rs0; y0 *= rs0; x1 *= rs1; y1 *= rs1; }
            if (MODE == 3) {
                const float2 bv = *(const float2*)&aux1[c];
                const float2 q0 = *(const float2*)&aux2[(long long)r0 * ldc + c];
                const float2 q1 = *(const float2*)&aux2[(long long)r1 * ldc + c];
                x0 += bv.x + q0.x; y0 += bv.y + q0.y;
                x1 += bv.x + q1.x; y1 += bv.y + q1.y;
            }
            if (MODE == 0) {
                float* Cf = (float*)Cg + (long long)blockIdx.z * sC;
                *(float2*)&Cf[(long long)r0 * ldc + c] = make_float2(x0, y0);
                *(float2*)&Cf[(long long)r1 * ldc + c] = make_float2(x1, y1);
            } else {
                f16* Cb = (f16*)Cg + (long long)blockIdx.z * sC;
                *(f162*)&Cb[(long long)r0 * ldc + c] = __floats2half2_rn(x0, y0);
                *(f162*)&Cb[(long long)r1 * ldc + c] = __floats2half2_rn(x1, y1);
            }
        }
    }
}

// ================= int8 QK^T with fused exp2 =================
// S[m,n] = exp2( (Qi8[m,:] . Ki8[n,:]) * sQ[m] * sK[n] * escale2 ) -> fp16
// K = 512 int8; CTA 128x128; k-chunk 128 bytes/stage; 3-stage cp.async.
#define QSTAGE 32768
#define QSMEM  (3 * QSTAGE)

__global__ void __launch_bounds__(256, 2)
qk_i8(const int8_t* __restrict__ Qg, const int8_t* __restrict__ Kg,
      f16* __restrict__ Sg, const float* __restrict__ sQ,
      const float* __restrict__ sK, float escale2)
{
    extern __shared__ char smc[];
    const uint32_t sm0 = smem_u32(smc);
    const int tid  = threadIdx.x;
    const int wid  = tid >> 5;
    const int lane = tid & 31;
    const int wm = wid >> 2;
    const int wn = wid & 3;
    const int m0 = blockIdx.y * 128;
    const int n0 = blockIdx.x * 128;
    const int z  = blockIdx.z;

    const int8_t* Abase = Qg + (long long)(z * SQ + m0) * HIDDEN;
    const int8_t* Bbase = Kg + (long long)(z * SKV + n0) * HIDDEN;

    const int crow = tid >> 3;
    const int ccol = tid & 7;

    int acc[4][4][4];
    #pragma unroll
    for (int a = 0; a < 4; a++)
        #pragma unroll
        for (int b = 0; b < 4; b++)
            #pragma unroll
            for (int c = 0; c < 4; c++) acc[a][b][c] = 0;

    const int KT = HIDDEN >> 7;   // 4 chunks of 128 int8

    auto load_stage = [&](int st, int kt) {
        const uint32_t sa = sm0 + st * QSTAGE;
        const uint32_t sb = sa + 16384;
        const int kofs = kt * 128;
        #pragma unroll
        for (int i = 0; i < 4; i++) {
            const int row = crow + i * 32;
            const uint32_t soff = SWZ128((uint32_t)(row * 128 + ccol * 16));
            cpa16(sa + soff, Abase + (long long)row * HIDDEN + kofs + ccol * 16);
            cpa16(sb + soff, Bbase + (long long)row * HIDDEN + kofs + ccol * 16);
        }
    };

    load_stage(0, 0); cpa_commit();
    load_stage(1, 1); cpa_commit();

    int st = 0;
    for (int kt = 0; kt < KT; ++kt) {
        cpa_wait<1>();
        __syncthreads();

        const uint32_t sa = sm0 + st * QSTAGE;
        const uint32_t sb = sa + 16384;

        #pragma unroll
        for (int ks = 0; ks < 4; ks++) {       // k=32 int8 per step
            uint32_t afr[4][4];
            uint32_t bfr[4][2];
            const int bcol = ks * 32 + ((lane >> 4) << 4);
            #pragma unroll
            for (int mt = 0; mt < 4; mt++) {
                const int row = wm * 64 + mt * 16 + (lane & 15);
                ldsm_x4(sa + SWZ128((uint32_t)(row * 128 + bcol)),
                        afr[mt][0], afr[mt][1], afr[mt][2], afr[mt][3]);
            }
            #pragma unroll
            for (int np = 0; np < 2; np++) {
                const int row = wn * 32 + np * 16 + (lane & 15);
                uint32_t r0, r1, r2, r3;
                ldsm_x4(sb + SWZ128((uint32_t)(row * 128 + bcol)), r0, r1, r2, r3);
                bfr[2*np][0] = r0;   bfr[2*np][1] = r2;
                bfr[2*np+1][0] = r1; bfr[2*np+1][1] = r3;
            }
            #pragma unroll
            for (int mt = 0; mt < 4; mt++)
                #pragma unroll
                for (int nt = 0; nt < 4; nt++)
                    imma16832(acc[mt][nt], afr[mt], bfr[nt]);
        }

        if (kt + 2 < KT) {
            int nst = st + 2; if (nst >= 3) nst -= 3;
            load_stage(nst, kt + 2);
        }
        cpa_commit();
        if (++st == 3) st = 0;
    }

    // epilogue: exp2(acc * sQ[r] * sK[c] * escale2) -> fp16
    f16* Srow = Sg + (long long)z * SQ * SKV;
    const float* sQz = sQ + z * SQ;
    const float* sKz = sK + z * SKV;

    #pragma unroll
    for (int mt = 0; mt < 4; mt++) {
        const int r0 = m0 + wm * 64 + mt * 16 + (lane >> 2);
        const int r1 = r0 + 8;
        const float q0 = sQz[r0] * escale2;
        const float q1 = sQz[r1] * escale2;
        #pragma unroll
        for (int nt = 0; nt < 4; nt++) {
            const int c = n0 + wn * 32 + nt * 8 + (lane & 3) * 2;
            const float2 kc = *(const float2*)&sKz[c];
            float x0 = ex2_mufu((float)acc[mt][nt][0] * q0 * kc.x);
            float y0 = ex2_mufu((float)acc[mt][nt][1] * q0 * kc.y);
            float x1 = ex2_mufu((float)acc[mt][nt][2] * q1 * kc.x);
            float y1 = ex2_mufu((float)acc[mt][nt][3] * q1 * kc.y);
            *(f162*)&Srow[(long long)r0 * SKV + c] = __floats2half2_rn(x0, y0);
            *(f162*)&Srow[(long long)r1 * SKV + c] = __floats2half2_rn(x1, y1);
        }
    }
}

// ============ per-row int8 quantization of fp16 [rows, 512] ============
// blockIdx.y selects (X0->Y0,s0) or (X1->Y1,s1). 256 threads, 2 elems each.
__global__ void quant_rows(const f16* __restrict__ X0, const f16* __restrict__ X1,
                           int8_t* __restrict__ Y0, int8_t* __restrict__ Y1,
                           float* __restrict__ s0, float* __restrict__ s1)
{
    const f16* X = blockIdx.y ? X1 : X0;
    int8_t*    Y = blockIdx.y ? Y1 : Y0;
    float*     s = blockIdx.y ? s1 : s0;
    const long long row = blockIdx.x;
    const int t = threadIdx.x;
    __shared__ float sh[32];

    const f162 v = ((const f162*)(X + row * HIDDEN))[t];
    float2 f = __half22float2(v);
    float m = fmaxf(fabsf(f.x), fabsf(f.y));
    #pragma unroll
    for (int o = 16; o; o >>= 1) m = fmaxf(m, __shfl_xor_sync(0xFFFFFFFFu, m, o));
    if ((t & 31) == 0) sh[t >> 5] = m;
    __syncthreads();
    if (t < 32) {
        float r = (t < 8) ? sh[t] : 0.0f;
        #pragma unroll
        for (int o = 4; o; o >>= 1) r = fmaxf(r, __shfl_xor_sync(0xFFFFFFFFu, r, o));
        if (t == 0) sh[0] = fmaxf(r, 1e-8f);
    }
    __syncthreads();
    const float M = sh[0];
    const float inv = 127.0f / M;

    char2 o;
    o.x = (char)__float2int_rn(f.x * inv);
    o.y = (char)__float2int_rn(f.y * inv);
    ((char2*)(Y + row * HIDDEN))[t] = o;
    if (t == 0) s[row] = M * (1.0f / 127.0f);
}

// ============ fp32 -> fp16 convert; blockIdx.y selects tensor ============
__global__ void conv_hi2(const float* __restrict__ X0, const float* __restrict__ X1,
                         f16* __restrict__ Y0, f16* __restrict__ Y1)
{
    const float* X = blockIdx.y ? X1 : X0;
    f16*         Y = blockIdx.y ? Y1 : Y0;
    const long long i4 = (long long)blockIdx.x * blockDim.x + threadIdx.x;
    float4 v = ((const float4*)X)[i4];
    ((f162*)Y)[i4 * 2]     = __floats2half2_rn(v.x, v.y);
    ((f162*)Y)[i4 * 2 + 1] = __floats2half2_rn(v.z, v.w);
}

// ============ transpose + fp16: In[R,C] fp32 -> Out[C,R] fp16 ============
__global__ void w3tr(const float* __restrict__ A0, const float* __restrict__ A1,
                     const float* __restrict__ A2,
                     f16* __restrict__ B0, f16* __restrict__ B1,
                     f16* __restrict__ B2, int R, int C)
{
    const float* In = (blockIdx.z == 0) ? A0 : (blockIdx.z == 1) ? A1 : A2;
    f16* Out = (blockIdx.z == 0) ? B0 : (blockIdx.z == 1) ? B1 : B2;
    __shared__ float t[32][33];
    const int bx = blockIdx.x * 32;
    const int by = blockIdx.y * 32;
    const int tx = threadIdx.x, ty = threadIdx.y;
    #pragma unroll
    for (int i = ty; i < 32; i += 8)
        t[i][tx] = In[(long long)(by + i) * C + bx + tx];
    __syncthreads();
    #pragma unroll
    for (int i = ty; i < 32; i += 8)
        Out[(long long)(bx + i) * R + by + tx] = __float2half_rn(t[tx][i]);
}

// ================= reductions =================
__device__ __forceinline__ float blockReduceSum(float v, float* sh)
{
    const int t = threadIdx.x;
    #pragma unroll
    for (int o = 16; o; o >>= 1) v += __shfl_xor_sync(0xFFFFFFFFu, v, o);
    if ((t & 31) == 0) sh[t >> 5] = v;
    __syncthreads();
    if (t < 32) {
        float r = (t < 8) ? sh[t] : 0.0f;
        #pragma unroll
        for (int o = 4; o; o >>= 1) r += __shfl_xor_sync(0xFFFFFFFFu, r, o);
        if (t == 0) sh[0] = r;
    }
    __syncthreads();
    float r = sh[0];
    __syncthreads();
    return r;
}

// ===== row sums of unnormalized exp-scores -> Zinv =====
__global__ void sumexp_kernel(const f16* __restrict__ S, float* __restrict__ Zi)
{
    const f162* p = (const f162*)(S + (long long)blockIdx.x * SKV);
    const int t = threadIdx.x;
    __shared__ float sh[32];
    float s = 0.0f;
    #pragma unroll
    for (int i = 0; i < 8; i++) {
        float2 v = __half22float2(p[t + 256 * i]);
        s += v.x + v.y;
    }
    s = blockReduceSum(s, sh);
    if (t == 0) Zi[blockIdx.x] = 1.0f / s;
}

// ================= layernorm =================
__global__ void layernorm_kernel(const float* __restrict__ X,
                                 const float* __restrict__ gamma,
                                 const float* __restrict__ beta,
                                 float* __restrict__ Y)
{
    const float* x = X + (long long)blockIdx.x * EMBED;
    float*       y = Y + (long long)blockIdx.x * EMBED;
    const int t = threadIdx.x;
    __shared__ float sh[32];

    float4 v = *(const float4*)&x[t * 4];
    float s = v.x + v.y + v.z + v.w;
    s = blockReduceSum(s, sh);
    const float mu = s * (1.0f / EMBED);

    float dx = v.x - mu, dy = v.y - mu, dz = v.z - mu, dw = v.w - mu;
    float sq = dx * dx + dy * dy + dz * dz + dw * dw;
    sq = blockReduceSum(sq, sh);
    const float rstd = rsqrtf(sq * (1.0f / EMBED) + 1e-5f);

    float4 g = *(const float4*)&gamma[t * 4];
    float4 b = *(const float4*)&beta[t * 4];
    float4 o;
    o.x = dx * rstd * g.x + b.x;
    o.y = dy * rstd * g.y + b.y;
    o.z = dz * rstd * g.z + b.z;
    o.w = dw * rstd * g.w + b.w;
    *(float4*)&y[t * 4] = o;
}

// ================= launch =================
extern "C" void kernel_launch(void* const* d_in, const int* in_sizes, int n_in,
                              void* d_out, int out_size)
{
    const float* q_feat = (const float*)d_in[0];
    const float* kv     = (const float*)d_in[1];
    const float* Wq     = (const float*)d_in[2];
    const float* Wk     = (const float*)d_in[3];
    const float* Wv     = (const float*)d_in[4];
    const float* Wo     = (const float*)d_in[5];
    const float* bo     = (const float*)d_in[6];
    const float* Wfc    = (const float*)d_in[7];
    const float* gamma  = (const float*)d_in[8];
    const float* beta   = (const float*)d_in[9];
    float* out = (float*)d_out;

    f16 *qfh, *kvh, *Qh, *Kh, *VT, *S, *Ch, *O1h, *Wq1, *Wk1, *Wv1, *Wo1, *Wfc1;
    int8_t *Qi, *Ki;
    float *sQ, *sK, *Zi, *O2;
    cudaGetSymbolAddress((void**)&qfh,  g_qfh);
    cudaGetSymbolAddress((void**)&kvh,  g_kvh);
    cudaGetSymbolAddress((void**)&Qh,   g_Qh);
    cudaGetSymbolAddress((void**)&Kh,   g_Kh);
    cudaGetSymbolAddress((void**)&Qi,   g_Qi);
    cudaGetSymbolAddress((void**)&Ki,   g_Ki);
    cudaGetSymbolAddress((void**)&sQ,   g_sQ);
    cudaGetSymbolAddress((void**)&sK,   g_sK);
    cudaGetSymbolAddress((void**)&VT,   g_VT);
    cudaGetSymbolAddress((void**)&S,    g_S);
    cudaGetSymbolAddress((void**)&Zi,   g_Zi);
    cudaGetSymbolAddress((void**)&Ch,   g_Ch);
    cudaGetSymbolAddress((void**)&O1h,  g_O1h);
    cudaGetSymbolAddress((void**)&O2,   g_O2);
    cudaGetSymbolAddress((void**)&Wq1,  g_Wq1);
    cudaGetSymbolAddress((void**)&Wk1,  g_Wk1);
    cudaGetSymbolAddress((void**)&Wv1,  g_Wv1);
    cudaGetSymbolAddress((void**)&Wo1,  g_Wo1);
    cudaGetSymbolAddress((void**)&Wfc1, g_Wfc1);

    cudaFuncSetAttribute(gemm_nt<0>, cudaFuncAttributeMaxDynamicSharedMemorySize, GSMEM);
    cudaFuncSetAttribute(gemm_nt<3>, cudaFuncAttributeMaxDynamicSharedMemorySize, GSMEM);
    cudaFuncSetAttribute(gemm_nt<4>, cudaFuncAttributeMaxDynamicSharedMemorySize, GSMEM);
    cudaFuncSetAttribute(gemm_nt<5>, cudaFuncAttributeMaxDynamicSharedMemorySize, GSMEM);
    cudaFuncSetAttribute(qk_i8, cudaFuncAttributeMaxDynamicSharedMemorySize, QSMEM);

    const dim3 blk(256);
    const dim3 tblk(32, 8);
    // exp(s/sqrt(512)) = 2^(s * escale2)
    const float escale2 = 0.044194173824159216f * 1.4426950408889634f;

    // launch 0: fp32 -> fp16 converts (both tensors)
    conv_hi2<<<dim3(MTOK * EMBED / 4 / 256, 2), 256>>>(q_feat, kv, qfh, kvh);
    // launch 1: fused Wq/Wk/Wv transpose
    w3tr<<<dim3(HIDDEN/32, EMBED/32, 3), tblk>>>(Wq, Wk, Wv, Wq1, Wk1, Wv1,
                                                 EMBED, HIDDEN);
    // launch 2: Q = qf @ Wq
    gemm_nt<4><<<dim3(HIDDEN/128, MTOK/128, 1), blk, GSMEM>>>(
        qfh, Wq1, Qh, EMBED, EMBED, EMBED, HIDDEN, 0, 0, 0, nullptr, nullptr, 0, 0.f);
    // launch 3: K = kv @ Wk
    gemm_nt<4><<<dim3(HIDDEN/128, MTOK/128, 1), blk, GSMEM>>>(
        kvh, Wk1, Kh, EMBED, EMBED, EMBED, HIDDEN, 0, 0, 0, nullptr, nullptr, 0, 0.f);
    // launch 4: per-row int8 quantization of Q and K
    quant_rows<<<dim3(MTOK, 2), 256>>>(Qh, Kh, Qi, Ki, sQ, sK);
    // launch 5 (profiled): S = exp2(QK^T int8 * scales) per batch
    qk_i8<<<dim3(SKV/128, SQ/128, NB), blk, QSMEM>>>(Qi, Ki, S, sQ, sK, escale2);
    // launch 6: VT[h,t] = sum_e Wv1[h,e] * kvh[t,e]
    gemm_nt<4><<<dim3(MTOK/128, HIDDEN/128, 1), blk, GSMEM>>>(
        Wv1, kvh, VT, EMBED, EMBED, EMBED, MTOK, 0, 0, 0, nullptr, nullptr, 0, 0.f);
    // launch 7: row sums -> Zinv
    sumexp_kernel<<<MTOK, 256>>>(S, Zi);
    // launch 8: ctx = (S @ V) * Zinv per batch
    gemm_nt<5><<<dim3(HIDDEN/128, SQ/128, NB), blk, GSMEM>>>(
        S, VT, Ch, SKV, SKV, MTOK, HIDDEN,
        (long long)SQ * SKV, (long long)SQ, (long long)SQ * HIDDEN,
        Zi, nullptr, SQ, 0.f);
    // launch 9: Wo^T transpose
    w3tr<<<dim3(EMBED/32, HIDDEN/32, 1), tblk>>>(Wo, Wo, Wo, Wo1, Wo1, Wo1,
                                                 HIDDEN, EMBED);
    // launch 10: O1 = ctx @ Wo + bo + q_feat -> fp16
    gemm_nt<3><<<dim3(EMBED/128, MTOK/128, 1), blk, GSMEM>>>(
        Ch, Wo1, O1h, HIDDEN, HIDDEN, HIDDEN, EMBED, 0, 0, 0, bo, q_feat, 0, 0.f);
    // launch 11: Wfc^T transpose
    w3tr<<<dim3(EMBED/32, EMBED/32, 1), tblk>>>(Wfc, Wfc, Wfc, Wfc1, Wfc1, Wfc1,
                                                EMBED, EMBED);
    // launch 12: O2 = O1 @ Wfc -> fp32
    gemm_nt<0><<<dim3(EMBED/128, MTOK/128, 1), blk, GSMEM>>>(
        O1h, Wfc1, O2, EMBED, EMBED, EMBED, EMBED, 0, 0, 0, nullptr, nullptr, 0, 0.f);
    // launch 13: layernorm -> out
    layernorm_kernel<<<MTOK, 256>>>(O2, gamma, beta, out);
}

// round 9
// speedup vs baseline: 1.3832x; 1.3832x over previous
#include <cuda_runtime.h>
#include <cuda_fp16.h>
#include <cstdint>
#include <math.h>

#define EMBED  1024
#define HIDDEN 512
#define NB     4
#define SQ     4096
#define SKV    4096
#define MTOK   (NB * SQ)   // 16384

typedef __half  f16;
typedef __half2 f162;

// ---------------- scratch (static device arrays; no allocations) ----------------
__device__ f16  g_qfh [(size_t)MTOK * EMBED];        // fp16 q_feat
__device__ f16  g_kvh [(size_t)MTOK * EMBED];        // fp16 kv_feat
__device__ f16  g_Qh  [(size_t)MTOK * HIDDEN];       // fp16 Q
__device__ f16  g_Kh  [(size_t)MTOK * HIDDEN];       // fp16 K
__device__ f16  g_VT  [(size_t)HIDDEN * MTOK];       // fp16 V^T [H, tokens]
__device__ f16  g_S   [(size_t)NB * SQ * SKV];       // unnormalized exp-scores
__device__ float g_Zi [MTOK];                        // row sums (atomic)
__device__ f16  g_Ch  [(size_t)MTOK * HIDDEN];       // fp16 ctx
__device__ f16  g_O1h [(size_t)MTOK * EMBED];        // fp16 O1 (ctx@Wo+bo+qf)
__device__ float g_O2 [(size_t)MTOK * EMBED];        // fp32 pre-LN
__device__ f16  g_Wq1 [(size_t)HIDDEN * EMBED];      // fp16 Wq^T
__device__ f16  g_Wk1 [(size_t)HIDDEN * EMBED];
__device__ f16  g_Wv1 [(size_t)HIDDEN * EMBED];
__device__ f16  g_Wo1 [(size_t)EMBED * HIDDEN];      // fp16 Wo^T
__device__ f16  g_Wfc1[(size_t)EMBED * EMBED];       // fp16 Wfc^T

// ================= helpers =================
__device__ __forceinline__ uint32_t smem_u32(const void* p) {
    return (uint32_t)__cvta_generic_to_shared((void*)p);
}
#define SWZ128(o) ((o) ^ (((o) >> 3) & 0x70))

__device__ __forceinline__ void cpa16(uint32_t s, const void* g) {
    asm volatile("cp.async.cg.shared.global [%0], [%1], 16;" :: "r"(s), "l"(g));
}
__device__ __forceinline__ void cpa_commit() {
    asm volatile("cp.async.commit_group;" ::: "memory");
}
template <int N> __device__ __forceinline__ void cpa_wait() {
    asm volatile("cp.async.wait_group %0;" :: "n"(N) : "memory");
}
__device__ __forceinline__ void ldsm_x4(uint32_t a, uint32_t& r0, uint32_t& r1,
                                        uint32_t& r2, uint32_t& r3) {
    asm volatile("ldmatrix.sync.aligned.m8n8.x4.shared.b16 {%0,%1,%2,%3}, [%4];"
                 : "=r"(r0), "=r"(r1), "=r"(r2), "=r"(r3) : "r"(a));
}
__device__ __forceinline__ void mma16816(float* c, const uint32_t* a, const uint32_t* b) {
    asm volatile("mma.sync.aligned.m16n8k16.row.col.f32.f16.f16.f32 "
                 "{%0,%1,%2,%3}, {%4,%5,%6,%7}, {%8,%9}, {%0,%1,%2,%3};"
                 : "+f"(c[0]), "+f"(c[1]), "+f"(c[2]), "+f"(c[3])
                 : "r"(a[0]), "r"(a[1]), "r"(a[2]), "r"(a[3]), "r"(b[0]), "r"(b[1]));
}
// fp16-accumulator HMMA (2 C/D regs of half2)
__device__ __forceinline__ void mma16816h(uint32_t* c, const uint32_t* a, const uint32_t* b) {
    asm volatile("mma.sync.aligned.m16n8k16.row.col.f16.f16.f16.f16 "
                 "{%0,%1}, {%2,%3,%4,%5}, {%6,%7}, {%0,%1};"
                 : "+r"(c[0]), "+r"(c[1])
                 : "r"(a[0]), "r"(a[1]), "r"(a[2]), "r"(a[3]), "r"(b[0]), "r"(b[1]));
}
__device__ __forceinline__ float ex2_mufu(float t) {
    float r;
    asm("ex2.approx.f32 %0, %1;" : "=f"(r) : "f"(t));
    return r;
}

// ================= fp16 NT GEMM (f32 acc) =================
// MODE 0: fp32 store
// MODE 3: +bias[col]+res[row,col] (fp32) -> fp16 store
// MODE 4: fp16 store
// MODE 5: acc / rowsum[z*sAux + r] -> fp16 store
#define STAGE_B 32768
#define GSMEM   (3 * STAGE_B)   // 98304

template <int MODE>
__global__ void __launch_bounds__(256, 2)
gemm_nt(const f16* __restrict__ Ag, const f16* __restrict__ Bg,
        void* __restrict__ Cg, int Kp, int lda, int ldb, int ldc,
        long long sA, long long sB, long long sC,
        const float* __restrict__ aux1, const float* __restrict__ aux2,
        long long sAux)
{
    extern __shared__ char smc[];
    const uint32_t sm0 = smem_u32(smc);
    const int tid  = threadIdx.x;
    const int wid  = tid >> 5;
    const int lane = tid & 31;
    const int wm = wid >> 2;
    const int wn = wid & 3;
    const int m0 = blockIdx.y * 128;
    const int n0 = blockIdx.x * 128;

    Ag += (long long)blockIdx.z * sA;
    Bg += (long long)blockIdx.z * sB;

    const f16* Abase = Ag + (long long)m0 * lda;
    const f16* Bbase = Bg + (long long)n0 * ldb;

    const int crow = tid >> 3;
    const int ccol = tid & 7;

    float acc[4][4][4];
    #pragma unroll
    for (int a = 0; a < 4; a++)
        #pragma unroll
        for (int b = 0; b < 4; b++)
            #pragma unroll
            for (int c = 0; c < 4; c++) acc[a][b][c] = 0.0f;

    const int KT = Kp >> 6;

    auto load_stage = [&](int st, int kt) {
        const uint32_t sa = sm0 + st * STAGE_B;
        const uint32_t sb = sa + 16384;
        const int kofs = kt * 64;
        #pragma unroll
        for (int i = 0; i < 4; i++) {
            const int row = crow + i * 32;
            const uint32_t soff = SWZ128((uint32_t)(row * 128 + ccol * 16));
            cpa16(sa + soff, Abase + (long long)row * lda + kofs + ccol * 8);
            cpa16(sb + soff, Bbase + (long long)row * ldb + kofs + ccol * 8);
        }
    };

    load_stage(0, 0); cpa_commit();
    load_stage(1, 1); cpa_commit();

    int st = 0;
    for (int kt = 0; kt < KT; ++kt) {
        cpa_wait<1>();
        __syncthreads();

        const uint32_t sa = sm0 + st * STAGE_B;
        const uint32_t sb = sa + 16384;

        #pragma unroll
        for (int ks = 0; ks < 4; ks++) {
            uint32_t afr[4][4];
            uint32_t bfr[4][2];
            const int bcol = ks * 32 + ((lane >> 4) << 4);
            #pragma unroll
            for (int mt = 0; mt < 4; mt++) {
                const int row = wm * 64 + mt * 16 + (lane & 15);
                ldsm_x4(sa + SWZ128((uint32_t)(row * 128 + bcol)),
                        afr[mt][0], afr[mt][1], afr[mt][2], afr[mt][3]);
            }
            #pragma unroll
            for (int np = 0; np < 2; np++) {
                const int row = wn * 32 + np * 16 + (lane & 15);
                uint32_t r0, r1, r2, r3;
                ldsm_x4(sb + SWZ128((uint32_t)(row * 128 + bcol)), r0, r1, r2, r3);
                bfr[2*np][0] = r0;   bfr[2*np][1] = r2;
                bfr[2*np+1][0] = r1; bfr[2*np+1][1] = r3;
            }
            #pragma unroll
            for (int mt = 0; mt < 4; mt++)
                #pragma unroll
                for (int nt = 0; nt < 4; nt++)
                    mma16816(acc[mt][nt], afr[mt], bfr[nt]);
        }

        if (kt + 2 < KT) {
            int nst = st + 2; if (nst >= 3) nst -= 3;
            load_stage(nst, kt + 2);
        }
        cpa_commit();
        if (++st == 3) st = 0;
    }

    const float* rs = (MODE == 5) ? (aux1 + (long long)blockIdx.z * sAux) : nullptr;

    #pragma unroll
    for (int mt = 0; mt < 4; mt++) {
        const int r0 = m0 + wm * 64 + mt * 16 + (lane >> 2);
        const int r1 = r0 + 8;
        float rs0 = 1.0f, rs1 = 1.0f;
        if (MODE == 5) { rs0 = 1.0f / rs[r0]; rs1 = 1.0f / rs[r1]; }
        #pragma unroll
        for (int nt = 0; nt < 4; nt++) {
            const int c = n0 + wn * 32 + nt * 8 + (lane & 3) * 2;
            float x0 = acc[mt][nt][0], y0 = acc[mt][nt][1];
            float x1 = acc[mt][nt][2], y1 = acc[mt][nt][3];
            if (MODE == 5) { x0 *= rs0; y0 *= rs0; x1 *= rs1; y1 *= rs1; }
            if (MODE == 3) {
                const float2 bv = *(const float2*)&aux1[c];
                const float2 q0 = *(const float2*)&aux2[(long long)r0 * ldc + c];
                const float2 q1 = *(const float2*)&aux2[(long long)r1 * ldc + c];
                x0 += bv.x + q0.x; y0 += bv.y + q0.y;
                x1 += bv.x + q1.x; y1 += bv.y + q1.y;
            }
            if (MODE == 0) {
                float* Cf = (float*)Cg + (long long)blockIdx.z * sC;
                *(float2*)&Cf[(long long)r0 * ldc + c] = make_float2(x0, y0);
                *(float2*)&Cf[(long long)r1 * ldc + c] = make_float2(x1, y1);
            } else {
                f16* Cb = (f16*)Cg + (long long)blockIdx.z * sC;
                *(f162*)&Cb[(long long)r0 * ldc + c] = __floats2half2_rn(x0, y0);
                *(f162*)&Cb[(long long)r1 * ldc + c] = __floats2half2_rn(x1, y1);
            }
        }
    }
}

// ================= QK^T (fp16 acc) + fused exp2 + atomic row sums =================
// S[m,n] = exp2(score * escale2); Zi[row] += row partial sums (pre-zeroed).
__global__ void __launch_bounds__(256, 2)
qk_f16(const f16* __restrict__ Qg, const f16* __restrict__ Kg,
       f16* __restrict__ Sg, float* __restrict__ Zi, float escale2)
{
    extern __shared__ char smc[];
    const uint32_t sm0 = smem_u32(smc);
    const int tid  = threadIdx.x;
    const int wid  = tid >> 5;
    const int lane = tid & 31;
    const int wm = wid >> 2;
    const int wn = wid & 3;
    const int m0 = blockIdx.y * 128;
    const int n0 = blockIdx.x * 128;
    const int z  = blockIdx.z;

    const f16* Abase = Qg + (long long)(z * SQ + m0) * HIDDEN;
    const f16* Bbase = Kg + (long long)(z * SKV + n0) * HIDDEN;

    const int crow = tid >> 3;
    const int ccol = tid & 7;

    uint32_t hacc[4][4][2];
    #pragma unroll
    for (int a = 0; a < 4; a++)
        #pragma unroll
        for (int b = 0; b < 4; b++) { hacc[a][b][0] = 0u; hacc[a][b][1] = 0u; }

    const int KT = HIDDEN >> 6;   // 8

    auto load_stage = [&](int st, int kt) {
        const uint32_t sa = sm0 + st * STAGE_B;
        const uint32_t sb = sa + 16384;
        const int kofs = kt * 64;
        #pragma unroll
        for (int i = 0; i < 4; i++) {
            const int row = crow + i * 32;
            const uint32_t soff = SWZ128((uint32_t)(row * 128 + ccol * 16));
            cpa16(sa + soff, Abase + (long long)row * HIDDEN + kofs + ccol * 8);
            cpa16(sb + soff, Bbase + (long long)row * HIDDEN + kofs + ccol * 8);
        }
    };

    load_stage(0, 0); cpa_commit();
    load_stage(1, 1); cpa_commit();

    int st = 0;
    for (int kt = 0; kt < KT; ++kt) {
        cpa_wait<1>();
        __syncthreads();

        const uint32_t sa = sm0 + st * STAGE_B;
        const uint32_t sb = sa + 16384;

        #pragma unroll
        for (int ks = 0; ks < 4; ks++) {
            uint32_t afr[4][4];
            uint32_t bfr[4][2];
            const int bcol = ks * 32 + ((lane >> 4) << 4);
            #pragma unroll
            for (int mt = 0; mt < 4; mt++) {
                const int row = wm * 64 + mt * 16 + (lane & 15);
                ldsm_x4(sa + SWZ128((uint32_t)(row * 128 + bcol)),
                        afr[mt][0], afr[mt][1], afr[mt][2], afr[mt][3]);
            }
            #pragma unroll
            for (int np = 0; np < 2; np++) {
                const int row = wn * 32 + np * 16 + (lane & 15);
                uint32_t r0, r1, r2, r3;
                ldsm_x4(sb + SWZ128((uint32_t)(row * 128 + bcol)), r0, r1, r2, r3);
                bfr[2*np][0] = r0;   bfr[2*np][1] = r2;
                bfr[2*np+1][0] = r1; bfr[2*np+1][1] = r3;
            }
            #pragma unroll
            for (int mt = 0; mt < 4; mt++)
                #pragma unroll
                for (int nt = 0; nt < 4; nt++)
                    mma16816h(hacc[mt][nt], afr[mt], bfr[nt]);
        }

        if (kt + 2 < KT) {
            int nst = st + 2; if (nst >= 3) nst -= 3;
            load_stage(nst, kt + 2);
        }
        cpa_commit();
        if (++st == 3) st = 0;
    }

    // epilogue: exp2(score * escale2) -> fp16 store + quad-reduced atomic row sums
    f16* Srow = Sg + (long long)z * SQ * SKV;
    float* Ziz = Zi + z * SQ;

    #pragma unroll
    for (int mt = 0; mt < 4; mt++) {
        const int r0 = m0 + wm * 64 + mt * 16 + (lane >> 2);
        const int r1 = r0 + 8;
        float rsum0 = 0.0f, rsum1 = 0.0f;
        #pragma unroll
        for (int nt = 0; nt < 4; nt++) {
            const int c = n0 + wn * 32 + nt * 8 + (lane & 3) * 2;
            const float2 v0 = __half22float2(*(f162*)&hacc[mt][nt][0]);
            const float2 v1 = __half22float2(*(f162*)&hacc[mt][nt][1]);
            float x0 = ex2_mufu(v0.x * escale2);
            float y0 = ex2_mufu(v0.y * escale2);
            float x1 = ex2_mufu(v1.x * escale2);
            float y1 = ex2_mufu(v1.y * escale2);
            rsum0 += x0 + y0;
            rsum1 += x1 + y1;
            *(f162*)&Srow[(long long)r0 * SKV + c] = __floats2half2_rn(x0, y0);
            *(f162*)&Srow[(long long)r1 * SKV + c] = __floats2half2_rn(x1, y1);
        }
        rsum0 += __shfl_xor_sync(0xFFFFFFFFu, rsum0, 1);
        rsum0 += __shfl_xor_sync(0xFFFFFFFFu, rsum0, 2);
        rsum1 += __shfl_xor_sync(0xFFFFFFFFu, rsum1, 1);
        rsum1 += __shfl_xor_sync(0xFFFFFFFFu, rsum1, 2);
        if ((lane & 3) == 0) {
            atomicAdd(&Ziz[r0], rsum0);
            atomicAdd(&Ziz[r1], rsum1);
        }
    }
}

// ============ zero fp32 buffer ============
__global__ void zero_f(float* __restrict__ p)
{
    p[blockIdx.x * 256 + threadIdx.x] = 0.0f;
}

// ============ fp32 -> fp16 convert; blockIdx.y selects tensor ============
__global__ void conv_hi2(const float* __restrict__ X0, const float* __restrict__ X1,
                         f16* __restrict__ Y0, f16* __restrict__ Y1)
{
    const float* X = blockIdx.y ? X1 : X0;
    f16*         Y = blockIdx.y ? Y1 : Y0;
    const long long i4 = (long long)blockIdx.x * blockDim.x + threadIdx.x;
    float4 v = ((const float4*)X)[i4];
    ((f162*)Y)[i4 * 2]     = __floats2half2_rn(v.x, v.y);
    ((f162*)Y)[i4 * 2 + 1] = __floats2half2_rn(v.z, v.w);
}

// ============ transpose + fp16: In[R,C] fp32 -> Out[C,R] fp16 ============
__global__ void w3tr(const float* __restrict__ A0, const float* __restrict__ A1,
                     const float* __restrict__ A2,
                     f16* __restrict__ B0, f16* __restrict__ B1,
                     f16* __restrict__ B2, int R, int C)
{
    const float* In = (blockIdx.z == 0) ? A0 : (blockIdx.z == 1) ? A1 : A2;
    f16* Out = (blockIdx.z == 0) ? B0 : (blockIdx.z == 1) ? B1 : B2;
    __shared__ float t[32][33];
    const int bx = blockIdx.x * 32;
    const int by = blockIdx.y * 32;
    const int tx = threadIdx.x, ty = threadIdx.y;
    #pragma unroll
    for (int i = ty; i < 32; i += 8)
        t[i][tx] = In[(long long)(by + i) * C + bx + tx];
    __syncthreads();
    #pragma unroll
    for (int i = ty; i < 32; i += 8)
        Out[(long long)(bx + i) * R + by + tx] = __float2half_rn(t[tx][i]);
}

// ================= reductions =================
__device__ __forceinline__ float blockReduceSum(float v, float* sh)
{
    const int t = threadIdx.x;
    #pragma unroll
    for (int o = 16; o; o >>= 1) v += __shfl_xor_sync(0xFFFFFFFFu, v, o);
    if ((t & 31) == 0) sh[t >> 5] = v;
    __syncthreads();
    if (t < 32) {
        float r = (t < 8) ? sh[t] : 0.0f;
        #pragma unroll
        for (int o = 4; o; o >>= 1) r += __shfl_xor_sync(0xFFFFFFFFu, r, o);
        if (t == 0) sh[0] = r;
    }
    __syncthreads();
    float r = sh[0];
    __syncthreads();
    return r;
}

// ================= layernorm =================
__global__ void layernorm_kernel(const float* __restrict__ X,
                                 const float* __restrict__ gamma,
                                 const float* __restrict__ beta,
                                 float* __restrict__ Y)
{
    const float* x = X + (long long)blockIdx.x * EMBED;
    float*       y = Y + (long long)blockIdx.x * EMBED;
    const int t = threadIdx.x;
    __shared__ float sh[32];

    float4 v = *(const float4*)&x[t * 4];
    float s = v.x + v.y + v.z + v.w;
    s = blockReduceSum(s, sh);
    const float mu = s * (1.0f / EMBED);

    float dx = v.x - mu, dy = v.y - mu, dz = v.z - mu, dw = v.w - mu;
    float sq = dx * dx + dy * dy + dz * dz + dw * dw;
    sq = blockReduceSum(sq, sh);
    const float rstd = rsqrtf(sq * (1.0f / EMBED) + 1e-5f);

    float4 g = *(const float4*)&gamma[t * 4];
    float4 b = *(const float4*)&beta[t * 4];
    float4 o;
    o.x = dx * rstd * g.x + b.x;
    o.y = dy * rstd * g.y + b.y;
    o.z = dz * rstd * g.z + b.z;
    o.w = dw * rstd * g.w + b.w;
    *(float4*)&y[t * 4] = o;
}

// ================= launch =================
extern "C" void kernel_launch(void* const* d_in, const int* in_sizes, int n_in,
                              void* d_out, int out_size)
{
    const float* q_feat = (const float*)d_in[0];
    const float* kv     = (const float*)d_in[1];
    const float* Wq     = (const float*)d_in[2];
    const float* Wk     = (const float*)d_in[3];
    const float* Wv     = (const float*)d_in[4];
    const float* Wo     = (const float*)d_in[5];
    const float* bo     = (const float*)d_in[6];
    const float* Wfc    = (const float*)d_in[7];
    const float* gamma  = (const float*)d_in[8];
    const float* beta   = (const float*)d_in[9];
    float* out = (float*)d_out;

    f16 *qfh, *kvh, *Qh, *Kh, *VT, *S, *Ch, *O1h, *Wq1, *Wk1, *Wv1, *Wo1, *Wfc1;
    float *Zi, *O2;
    cudaGetSymbolAddress((void**)&qfh,  g_qfh);
    cudaGetSymbolAddress((void**)&kvh,  g_kvh);
    cudaGetSymbolAddress((void**)&Qh,   g_Qh);
    cudaGetSymbolAddress((void**)&Kh,   g_Kh);
    cudaGetSymbolAddress((void**)&VT,   g_VT);
    cudaGetSymbolAddress((void**)&S,    g_S);
    cudaGetSymbolAddress((void**)&Zi,   g_Zi);
    cudaGetSymbolAddress((void**)&Ch,   g_Ch);
    cudaGetSymbolAddress((void**)&O1h,  g_O1h);
    cudaGetSymbolAddress((void**)&O2,   g_O2);
    cudaGetSymbolAddress((void**)&Wq1,  g_Wq1);
    cudaGetSymbolAddress((void**)&Wk1,  g_Wk1);
    cudaGetSymbolAddress((void**)&Wv1,  g_Wv1);
    cudaGetSymbolAddress((void**)&Wo1,  g_Wo1);
    cudaGetSymbolAddress((void**)&Wfc1, g_Wfc1);

    cudaFuncSetAttribute(gemm_nt<0>, cudaFuncAttributeMaxDynamicSharedMemorySize, GSMEM);
    cudaFuncSetAttribute(gemm_nt<3>, cudaFuncAttributeMaxDynamicSharedMemorySize, GSMEM);
    cudaFuncSetAttribute(gemm_nt<4>, cudaFuncAttributeMaxDynamicSharedMemorySize, GSMEM);
    cudaFuncSetAttribute(gemm_nt<5>, cudaFuncAttributeMaxDynamicSharedMemorySize, GSMEM);
    cudaFuncSetAttribute(qk_f16, cudaFuncAttributeMaxDynamicSharedMemorySize, GSMEM);

    const dim3 blk(256);
    const dim3 tblk(32, 8);
    // exp(s/sqrt(512)) = 2^(s * escale2)
    const float escale2 = 0.044194173824159216f * 1.4426950408889634f;

    // launch 0: fp32 -> fp16 converts (both tensors)
    conv_hi2<<<dim3(MTOK * EMBED / 4 / 256, 2), 256>>>(q_feat, kv, qfh, kvh);
    // launch 1: fused Wq/Wk/Wv transpose
    w3tr<<<dim3(HIDDEN/32, EMBED/32, 3), tblk>>>(Wq, Wk, Wv, Wq1, Wk1, Wv1,
                                                 EMBED, HIDDEN);
    // launch 2: zero Zi
    zero_f<<<MTOK / 256, 256>>>(Zi);
    // launch 3: Q = qf @ Wq
    gemm_nt<4><<<dim3(HIDDEN/128, MTOK/128, 1), blk, GSMEM>>>(
        qfh, Wq1, Qh, EMBED, EMBED, EMBED, HIDDEN, 0, 0, 0, nullptr, nullptr, 0);
    // launch 4: K = kv @ Wk
    gemm_nt<4><<<dim3(HIDDEN/128, MTOK/128, 1), blk, GSMEM>>>(
        kvh, Wk1, Kh, EMBED, EMBED, EMBED, HIDDEN, 0, 0, 0, nullptr, nullptr, 0);
    // launch 5 (profiled): S = exp2(QK^T * escale2), Zi += row sums
    qk_f16<<<dim3(SKV/128, SQ/128, NB), blk, GSMEM>>>(Qh, Kh, S, Zi, escale2);
    // launch 6: VT[h,t] = sum_e Wv1[h,e] * kvh[t,e]
    gemm_nt<4><<<dim3(MTOK/128, HIDDEN/128, 1), blk, GSMEM>>>(
        Wv1, kvh, VT, EMBED, EMBED, EMBED, MTOK, 0, 0, 0, nullptr, nullptr, 0);
    // launch 7: ctx = (S @ V) / Zi per batch
    gemm_nt<5><<<dim3(HIDDEN/128, SQ/128, NB), blk, GSMEM>>>(
        S, VT, Ch, SKV, SKV, MTOK, HIDDEN,
        (long long)SQ * SKV, (long long)SQ, (long long)SQ * HIDDEN,
        Zi, nullptr, SQ);
    // launch 8: Wo^T transpose
    w3tr<<<dim3(EMBED/32, HIDDEN/32, 1), tblk>>>(Wo, Wo, Wo, Wo1, Wo1, Wo1,
                                                 HIDDEN, EMBED);
    // launch 9: O1 = ctx @ Wo + bo + q_feat -> fp16
    gemm_nt<3><<<dim3(EMBED/128, MTOK/128, 1), blk, GSMEM>>>(
        Ch, Wo1, O1h, HIDDEN, HIDDEN, HIDDEN, EMBED, 0, 0, 0, bo, q_feat, 0);
    // launch 10: Wfc^T transpose
    w3tr<<<dim3(EMBED/32, EMBED/32, 1), tblk>>>(Wfc, Wfc, Wfc, Wfc1, Wfc1, Wfc1,
                                                EMBED, EMBED);
    // launch 11: O2 = O1 @ Wfc -> fp32
    gemm_nt<0><<<dim3(EMBED/128, MTOK/128, 1), blk, GSMEM>>>(
        O1h, Wfc1, O2, EMBED, EMBED, EMBED, EMBED, 0, 0, 0, nullptr, nullptr, 0);
    // launch 12: layernorm -> out
    layernorm_kernel<<<MTOK, 256>>>(O2, gamma, beta, out);
}

// round 10
// speedup vs baseline: 1.4217x; 1.0279x over previous
#include <cuda_runtime.h>
#include <cuda_fp16.h>
#include <cstdint>
#include <math.h>

#define EMBED  1024
#define HIDDEN 512
#define NB     4
#define SQ     4096
#define SKV    4096
#define MTOK   (NB * SQ)   // 16384

typedef __half  f16;
typedef __half2 f162;

// ---------------- scratch (static device arrays; no allocations) ----------------
__device__ f16  g_qfh [(size_t)MTOK * EMBED];        // fp16 q_feat
__device__ f16  g_kvh [(size_t)MTOK * EMBED];        // fp16 kv_feat
__device__ f16  g_Qh  [(size_t)MTOK * HIDDEN];       // fp16 Q
__device__ f16  g_Kh  [(size_t)MTOK * HIDDEN];       // fp16 K
__device__ f16  g_VT  [(size_t)HIDDEN * MTOK];       // fp16 V^T [H, tokens]
__device__ f16  g_S   [(size_t)NB * SQ * SKV];       // unnormalized exp-scores
__device__ float g_Zi [MTOK];                        // row sums (atomic)
__device__ f16  g_Ch  [(size_t)MTOK * HIDDEN];       // fp16 ctx
__device__ f16  g_O1h [(size_t)MTOK * EMBED];        // fp16 O1 (ctx@Wo+bo+qf)
__device__ float g_O2 [(size_t)MTOK * EMBED];        // fp32 pre-LN
__device__ f16  g_Wq1 [(size_t)HIDDEN * EMBED];      // fp16 Wq^T
__device__ f16  g_Wk1 [(size_t)HIDDEN * EMBED];
__device__ f16  g_Wv1 [(size_t)HIDDEN * EMBED];
__device__ f16  g_Wo1 [(size_t)EMBED * HIDDEN];      // fp16 Wo^T
__device__ f16  g_Wfc1[(size_t)EMBED * EMBED];       // fp16 Wfc^T

// ================= helpers =================
__device__ __forceinline__ uint32_t smem_u32(const void* p) {
    return (uint32_t)__cvta_generic_to_shared((void*)p);
}
#define SWZ128(o) ((o) ^ (((o) >> 3) & 0x70))

__device__ __forceinline__ void cpa16(uint32_t s, const void* g) {
    asm volatile("cp.async.cg.shared.global [%0], [%1], 16;" :: "r"(s), "l"(g));
}
__device__ __forceinline__ void cpa_commit() {
    asm volatile("cp.async.commit_group;" ::: "memory");
}
template <int N> __device__ __forceinline__ void cpa_wait() {
    asm volatile("cp.async.wait_group %0;" :: "n"(N) : "memory");
}
__device__ __forceinline__ void ldsm_x4(uint32_t a, uint32_t& r0, uint32_t& r1,
                                        uint32_t& r2, uint32_t& r3) {
    asm volatile("ldmatrix.sync.aligned.m8n8.x4.shared.b16 {%0,%1,%2,%3}, [%4];"
                 : "=r"(r0), "=r"(r1), "=r"(r2), "=r"(r3) : "r"(a));
}
__device__ __forceinline__ void mma16816(float* c, const uint32_t* a, const uint32_t* b) {
    asm volatile("mma.sync.aligned.m16n8k16.row.col.f32.f16.f16.f32 "
                 "{%0,%1,%2,%3}, {%4,%5,%6,%7}, {%8,%9}, {%0,%1,%2,%3};"
                 : "+f"(c[0]), "+f"(c[1]), "+f"(c[2]), "+f"(c[3])
                 : "r"(a[0]), "r"(a[1]), "r"(a[2]), "r"(a[3]), "r"(b[0]), "r"(b[1]));
}
// fp16-accumulator HMMA (2 C/D regs of half2)
__device__ __forceinline__ void mma16816h(uint32_t* c, const uint32_t* a, const uint32_t* b) {
    asm volatile("mma.sync.aligned.m16n8k16.row.col.f16.f16.f16.f16 "
                 "{%0,%1}, {%2,%3,%4,%5}, {%6,%7}, {%0,%1};"
                 : "+r"(c[0]), "+r"(c[1])
                 : "r"(a[0]), "r"(a[1]), "r"(a[2]), "r"(a[3]), "r"(b[0]), "r"(b[1]));
}
__device__ __forceinline__ float ex2_mufu(float t) {
    float r;
    asm("ex2.approx.f32 %0, %1;" : "=f"(r) : "f"(t));
    return r;
}

// ================= fp16 NT GEMM (f32 acc) =================
// MODE 0: fp32 store
// MODE 3: +bias[col]+res[row,col] (fp32) -> fp16 store
// MODE 4: fp16 store
// MODE 5: acc / rowsum[z*sAux + r] -> fp16 store
#define STAGE_B 32768
#define GSMEM   (3 * STAGE_B)   // 98304

template <int MODE>
__global__ void __launch_bounds__(256, 2)
gemm_nt(const f16* __restrict__ Ag, const f16* __restrict__ Bg,
        void* __restrict__ Cg, int Kp, int lda, int ldb, int ldc,
        long long sA, long long sB, long long sC,
        const float* __restrict__ aux1, const float* __restrict__ aux2,
        long long sAux)
{
    extern __shared__ char smc[];
    const uint32_t sm0 = smem_u32(smc);
    const int tid  = threadIdx.x;
    const int wid  = tid >> 5;
    const int lane = tid & 31;
    const int wm = wid >> 2;
    const int wn = wid & 3;
    const int m0 = blockIdx.y * 128;
    const int n0 = blockIdx.x * 128;

    Ag += (long long)blockIdx.z * sA;
    Bg += (long long)blockIdx.z * sB;

    const f16* Abase = Ag + (long long)m0 * lda;
    const f16* Bbase = Bg + (long long)n0 * ldb;

    const int crow = tid >> 3;
    const int ccol = tid & 7;

    float acc[4][4][4];
    #pragma unroll
    for (int a = 0; a < 4; a++)
        #pragma unroll
        for (int b = 0; b < 4; b++)
            #pragma unroll
            for (int c = 0; c < 4; c++) acc[a][b][c] = 0.0f;

    const int KT = Kp >> 6;

    auto load_stage = [&](int st, int kt) {
        const uint32_t sa = sm0 + st * STAGE_B;
        const uint32_t sb = sa + 16384;
        const int kofs = kt * 64;
        #pragma unroll
        for (int i = 0; i < 4; i++) {
            const int row = crow + i * 32;
            const uint32_t soff = SWZ128((uint32_t)(row * 128 + ccol * 16));
            cpa16(sa + soff, Abase + (long long)row * lda + kofs + ccol * 8);
            cpa16(sb + soff, Bbase + (long long)row * ldb + kofs + ccol * 8);
        }
    };

    load_stage(0, 0); cpa_commit();
    load_stage(1, 1); cpa_commit();

    int st = 0;
    for (int kt = 0; kt < KT; ++kt) {
        cpa_wait<1>();
        __syncthreads();

        const uint32_t sa = sm0 + st * STAGE_B;
        const uint32_t sb = sa + 16384;

        #pragma unroll
        for (int ks = 0; ks < 4; ks++) {
            uint32_t afr[4][4];
            uint32_t bfr[4][2];
            const int bcol = ks * 32 + ((lane >> 4) << 4);
            #pragma unroll
            for (int mt = 0; mt < 4; mt++) {
                const int row = wm * 64 + mt * 16 + (lane & 15);
                ldsm_x4(sa + SWZ128((uint32_t)(row * 128 + bcol)),
                        afr[mt][0], afr[mt][1], afr[mt][2], afr[mt][3]);
            }
            #pragma unroll
            for (int np = 0; np < 2; np++) {
                const int row = wn * 32 + np * 16 + (lane & 15);
                uint32_t r0, r1, r2, r3;
                ldsm_x4(sb + SWZ128((uint32_t)(row * 128 + bcol)), r0, r1, r2, r3);
                bfr[2*np][0] = r0;   bfr[2*np][1] = r2;
                bfr[2*np+1][0] = r1; bfr[2*np+1][1] = r3;
            }
            #pragma unroll
            for (int mt = 0; mt < 4; mt++)
                #pragma unroll
                for (int nt = 0; nt < 4; nt++)
                    mma16816(acc[mt][nt], afr[mt], bfr[nt]);
        }

        if (kt + 2 < KT) {
            int nst = st + 2; if (nst >= 3) nst -= 3;
            load_stage(nst, kt + 2);
        }
        cpa_commit();
        if (++st == 3) st = 0;
    }

    const float* rs = (MODE == 5) ? (aux1 + (long long)blockIdx.z * sAux) : nullptr;

    #pragma unroll
    for (int mt = 0; mt < 4; mt++) {
        const int r0 = m0 + wm * 64 + mt * 16 + (lane >> 2);
        const int r1 = r0 + 8;
        float rs0 = 1.0f, rs1 = 1.0f;
        if (MODE == 5) { rs0 = 1.0f / rs[r0]; rs1 = 1.0f / rs[r1]; }
        #pragma unroll
        for (int nt = 0; nt < 4; nt++) {
            const int c = n0 + wn * 32 + nt * 8 + (lane & 3) * 2;
            float x0 = acc[mt][nt][0], y0 = acc[mt][nt][1];
            float x1 = acc[mt][nt][2], y1 = acc[mt][nt][3];
            if (MODE == 5) { x0 *= rs0; y0 *= rs0; x1 *= rs1; y1 *= rs1; }
            if (MODE == 3) {
                const float2 bv = *(const float2*)&aux1[c];
                const float2 q0 = *(const float2*)&aux2[(long long)r0 * ldc + c];
                const float2 q1 = *(const float2*)&aux2[(long long)r1 * ldc + c];
                x0 += bv.x + q0.x; y0 += bv.y + q0.y;
                x1 += bv.x + q1.x; y1 += bv.y + q1.y;
            }
            if (MODE == 0) {
                float* Cf = (float*)Cg + (long long)blockIdx.z * sC;
                *(float2*)&Cf[(long long)r0 * ldc + c] = make_float2(x0, y0);
                *(float2*)&Cf[(long long)r1 * ldc + c] = make_float2(x1, y1);
            } else {
                f16* Cb = (f16*)Cg + (long long)blockIdx.z * sC;
                *(f162*)&Cb[(long long)r0 * ldc + c] = __floats2half2_rn(x0, y0);
                *(f162*)&Cb[(long long)r1 * ldc + c] = __floats2half2_rn(x1, y1);
            }
        }
    }
}

// ================= QK^T (fp16 acc) + fused exp2 + atomic row sums =================
__global__ void __launch_bounds__(256, 2)
qk_f16(const f16* __restrict__ Qg, const f16* __restrict__ Kg,
       f16* __restrict__ Sg, float* __restrict__ Zi, float escale2)
{
    extern __shared__ char smc[];
    const uint32_t sm0 = smem_u32(smc);
    const int tid  = threadIdx.x;
    const int wid  = tid >> 5;
    const int lane = tid & 31;
    const int wm = wid >> 2;
    const int wn = wid & 3;
    const int m0 = blockIdx.y * 128;
    const int n0 = blockIdx.x * 128;
    const int z  = blockIdx.z;

    const f16* Abase = Qg + (long long)(z * SQ + m0) * HIDDEN;
    const f16* Bbase = Kg + (long long)(z * SKV + n0) * HIDDEN;

    const int crow = tid >> 3;
    const int ccol = tid & 7;

    uint32_t hacc[4][4][2];
    #pragma unroll
    for (int a = 0; a < 4; a++)
        #pragma unroll
        for (int b = 0; b < 4; b++) { hacc[a][b][0] = 0u; hacc[a][b][1] = 0u; }

    const int KT = HIDDEN >> 6;   // 8

    auto load_stage = [&](int st, int kt) {
        const uint32_t sa = sm0 + st * STAGE_B;
        const uint32_t sb = sa + 16384;
        const int kofs = kt * 64;
        #pragma unroll
        for (int i = 0; i < 4; i++) {
            const int row = crow + i * 32;
            const uint32_t soff = SWZ128((uint32_t)(row * 128 + ccol * 16));
            cpa16(sa + soff, Abase + (long long)row * HIDDEN + kofs + ccol * 8);
            cpa16(sb + soff, Bbase + (long long)row * HIDDEN + kofs + ccol * 8);
        }
    };

    load_stage(0, 0); cpa_commit();
    load_stage(1, 1); cpa_commit();

    int st = 0;
    for (int kt = 0; kt < KT; ++kt) {
        cpa_wait<1>();
        __syncthreads();

        const uint32_t sa = sm0 + st * STAGE_B;
        const uint32_t sb = sa + 16384;

        #pragma unroll
        for (int ks = 0; ks < 4; ks++) {
            uint32_t afr[4][4];
            uint32_t bfr[4][2];
            const int bcol = ks * 32 + ((lane >> 4) << 4);
            #pragma unroll
            for (int mt = 0; mt < 4; mt++) {
                const int row = wm * 64 + mt * 16 + (lane & 15);
                ldsm_x4(sa + SWZ128((uint32_t)(row * 128 + bcol)),
                        afr[mt][0], afr[mt][1], afr[mt][2], afr[mt][3]);
            }
            #pragma unroll
            for (int np = 0; np < 2; np++) {
                const int row = wn * 32 + np * 16 + (lane & 15);
                uint32_t r0, r1, r2, r3;
                ldsm_x4(sb + SWZ128((uint32_t)(row * 128 + bcol)), r0, r1, r2, r3);
                bfr[2*np][0] = r0;   bfr[2*np][1] = r2;
                bfr[2*np+1][0] = r1; bfr[2*np+1][1] = r3;
            }
            #pragma unroll
            for (int mt = 0; mt < 4; mt++)
                #pragma unroll
                for (int nt = 0; nt < 4; nt++)
                    mma16816h(hacc[mt][nt], afr[mt], bfr[nt]);
        }

        if (kt + 2 < KT) {
            int nst = st + 2; if (nst >= 3) nst -= 3;
            load_stage(nst, kt + 2);
        }
        cpa_commit();
        if (++st == 3) st = 0;
    }

    // epilogue: exp2(score * escale2) -> fp16 store + quad-reduced atomic row sums
    f16* Srow = Sg + (long long)z * SQ * SKV;
    float* Ziz = Zi + z * SQ;

    #pragma unroll
    for (int mt = 0; mt < 4; mt++) {
        const int r0 = m0 + wm * 64 + mt * 16 + (lane >> 2);
        const int r1 = r0 + 8;
        float rsum0 = 0.0f, rsum1 = 0.0f;
        #pragma unroll
        for (int nt = 0; nt < 4; nt++) {
            const int c = n0 + wn * 32 + nt * 8 + (lane & 3) * 2;
            const float2 v0 = __half22float2(*(f162*)&hacc[mt][nt][0]);
            const float2 v1 = __half22float2(*(f162*)&hacc[mt][nt][1]);
            float x0 = ex2_mufu(v0.x * escale2);
            float y0 = ex2_mufu(v0.y * escale2);
            float x1 = ex2_mufu(v1.x * escale2);
            float y1 = ex2_mufu(v1.y * escale2);
            rsum0 += x0 + y0;
            rsum1 += x1 + y1;
            *(f162*)&Srow[(long long)r0 * SKV + c] = __floats2half2_rn(x0, y0);
            *(f162*)&Srow[(long long)r1 * SKV + c] = __floats2half2_rn(x1, y1);
        }
        rsum0 += __shfl_xor_sync(0xFFFFFFFFu, rsum0, 1);
        rsum0 += __shfl_xor_sync(0xFFFFFFFFu, rsum0, 2);
        rsum1 += __shfl_xor_sync(0xFFFFFFFFu, rsum1, 1);
        rsum1 += __shfl_xor_sync(0xFFFFFFFFu, rsum1, 2);
        if ((lane & 3) == 0) {
            atomicAdd(&Ziz[r0], rsum0);
            atomicAdd(&Ziz[r1], rsum1);
        }
    }
}

// ============ zero fp32 buffer ============
__global__ void zero_f(float* __restrict__ p)
{
    p[blockIdx.x * 256 + threadIdx.x] = 0.0f;
}

// ============ fp32 -> fp16 convert; blockIdx.y selects tensor ============
__global__ void conv_hi2(const float* __restrict__ X0, const float* __restrict__ X1,
                         f16* __restrict__ Y0, f16* __restrict__ Y1)
{
    const float* X = blockIdx.y ? X1 : X0;
    f16*         Y = blockIdx.y ? Y1 : Y0;
    const long long i4 = (long long)blockIdx.x * blockDim.x + threadIdx.x;
    float4 v = ((const float4*)X)[i4];
    ((f162*)Y)[i4 * 2]     = __floats2half2_rn(v.x, v.y);
    ((f162*)Y)[i4 * 2 + 1] = __floats2half2_rn(v.z, v.w);
}

// ============ all-weights transpose + fp16: z selects the tensor ============
// z: 0=Wq(1024x512) 1=Wk 2=Wv 3=Wo(512x1024) 4=Wfc(1024x1024); Out[C,R].
__global__ void w3tr_all(const float* __restrict__ Wq, const float* __restrict__ Wk,
                         const float* __restrict__ Wv, const float* __restrict__ Wo,
                         const float* __restrict__ Wfc,
                         f16* __restrict__ Oq, f16* __restrict__ Ok,
                         f16* __restrict__ Ov, f16* __restrict__ Oo,
                         f16* __restrict__ Ofc)
{
    const int z = blockIdx.z;
    const float* In;
    f16* Out;
    int R, C;
    if (z == 0)      { In = Wq;  Out = Oq;  R = 1024; C = 512; }
    else if (z == 1) { In = Wk;  Out = Ok;  R = 1024; C = 512; }
    else if (z == 2) { In = Wv;  Out = Ov;  R = 1024; C = 512; }
    else if (z == 3) { In = Wo;  Out = Oo;  R = 512;  C = 1024; }
    else             { In = Wfc; Out = Ofc; R = 1024; C = 1024; }

    const int bx = blockIdx.x * 32;   // C
    const int by = blockIdx.y * 32;   // R
    if (bx >= C || by >= R) return;

    __shared__ float t[32][33];
    const int tx = threadIdx.x, ty = threadIdx.y;
    #pragma unroll
    for (int i = ty; i < 32; i += 8)
        t[i][tx] = In[(long long)(by + i) * C + bx + tx];
    __syncthreads();
    #pragma unroll
    for (int i = ty; i < 32; i += 8)
        Out[(long long)(bx + i) * R + by + tx] = __float2half_rn(t[tx][i]);
}

// ================= reductions =================
__device__ __forceinline__ float blockReduceSum(float v, float* sh)
{
    const int t = threadIdx.x;
    #pragma unroll
    for (int o = 16; o; o >>= 1) v += __shfl_xor_sync(0xFFFFFFFFu, v, o);
    if ((t & 31) == 0) sh[t >> 5] = v;
    __syncthreads();
    if (t < 32) {
        float r = (t < 8) ? sh[t] : 0.0f;
        #pragma unroll
        for (int o = 4; o; o >>= 1) r += __shfl_xor_sync(0xFFFFFFFFu, r, o);
        if (t == 0) sh[0] = r;
    }
    __syncthreads();
    float r = sh[0];
    __syncthreads();
    return r;
}

// ================= layernorm =================
__global__ void layernorm_kernel(const float* __restrict__ X,
                                 const float* __restrict__ gamma,
                                 const float* __restrict__ beta,
                                 float* __restrict__ Y)
{
    const float* x = X + (long long)blockIdx.x * EMBED;
    float*       y = Y + (long long)blockIdx.x * EMBED;
    const int t = threadIdx.x;
    __shared__ float sh[32];

    float4 v = *(const float4*)&x[t * 4];
    float s = v.x + v.y + v.z + v.w;
    s = blockReduceSum(s, sh);
    const float mu = s * (1.0f / EMBED);

    float dx = v.x - mu, dy = v.y - mu, dz = v.z - mu, dw = v.w - mu;
    float sq = dx * dx + dy * dy + dz * dz + dw * dw;
    sq = blockReduceSum(sq, sh);
    const float rstd = rsqrtf(sq * (1.0f / EMBED) + 1e-5f);

    float4 g = *(const float4*)&gamma[t * 4];
    float4 b = *(const float4*)&beta[t * 4];
    float4 o;
    o.x = dx * rstd * g.x + b.x;
    o.y = dy * rstd * g.y + b.y;
    o.z = dz * rstd * g.z + b.z;
    o.w = dw * rstd * g.w + b.w;
    *(float4*)&y[t * 4] = o;
}

// ================= launch =================
extern "C" void kernel_launch(void* const* d_in, const int* in_sizes, int n_in,
                              void* d_out, int out_size)
{
    const float* q_feat = (const float*)d_in[0];
    const float* kv     = (const float*)d_in[1];
    const float* Wq     = (const float*)d_in[2];
    const float* Wk     = (const float*)d_in[3];
    const float* Wv     = (const float*)d_in[4];
    const float* Wo     = (const float*)d_in[5];
    const float* bo     = (const float*)d_in[6];
    const float* Wfc    = (const float*)d_in[7];
    const float* gamma  = (const float*)d_in[8];
    const float* beta   = (const float*)d_in[9];
    float* out = (float*)d_out;

    f16 *qfh, *kvh, *Qh, *Kh, *VT, *S, *Ch, *O1h, *Wq1, *Wk1, *Wv1, *Wo1, *Wfc1;
    float *Zi, *O2;
    cudaGetSymbolAddress((void**)&qfh,  g_qfh);
    cudaGetSymbolAddress((void**)&kvh,  g_kvh);
    cudaGetSymbolAddress((void**)&Qh,   g_Qh);
    cudaGetSymbolAddress((void**)&Kh,   g_Kh);
    cudaGetSymbolAddress((void**)&VT,   g_VT);
    cudaGetSymbolAddress((void**)&S,    g_S);
    cudaGetSymbolAddress((void**)&Zi,   g_Zi);
    cudaGetSymbolAddress((void**)&Ch,   g_Ch);
    cudaGetSymbolAddress((void**)&O1h,  g_O1h);
    cudaGetSymbolAddress((void**)&O2,   g_O2);
    cudaGetSymbolAddress((void**)&Wq1,  g_Wq1);
    cudaGetSymbolAddress((void**)&Wk1,  g_Wk1);
    cudaGetSymbolAddress((void**)&Wv1,  g_Wv1);
    cudaGetSymbolAddress((void**)&Wo1,  g_Wo1);
    cudaGetSymbolAddress((void**)&Wfc1, g_Wfc1);

    cudaFuncSetAttribute(gemm_nt<0>, cudaFuncAttributeMaxDynamicSharedMemorySize, GSMEM);
    cudaFuncSetAttribute(gemm_nt<3>, cudaFuncAttributeMaxDynamicSharedMemorySize, GSMEM);
    cudaFuncSetAttribute(gemm_nt<4>, cudaFuncAttributeMaxDynamicSharedMemorySize, GSMEM);
    cudaFuncSetAttribute(gemm_nt<5>, cudaFuncAttributeMaxDynamicSharedMemorySize, GSMEM);
    cudaFuncSetAttribute(qk_f16, cudaFuncAttributeMaxDynamicSharedMemorySize, GSMEM);

    const dim3 blk(256);
    const dim3 tblk(32, 8);
    const float escale2 = 0.044194173824159216f * 1.4426950408889634f;

    // side stream + fork/join events (fresh per call; no device allocations)
    cudaStream_t s1;
    cudaStreamCreate(&s1);
    cudaEvent_t eFork, eConv, eW3, eVT;
    cudaEventCreateWithFlags(&eFork, cudaEventDisableTiming);
    cudaEventCreateWithFlags(&eConv, cudaEventDisableTiming);
    cudaEventCreateWithFlags(&eW3,   cudaEventDisableTiming);
    cudaEventCreateWithFlags(&eVT,   cudaEventDisableTiming);

    // fork side stream from main stream
    cudaEventRecord(eFork, 0);
    cudaStreamWaitEvent(s1, eFork, 0);

    // L0 (main): fp32 -> fp16 converts (both activations)
    conv_hi2<<<dim3(MTOK * EMBED / 4 / 256, 2), 256>>>(q_feat, kv, qfh, kvh);
    cudaEventRecord(eConv, 0);

    // L1 (s1): all 5 weight transposes in one launch
    w3tr_all<<<dim3(32, 32, 5), tblk, 0, s1>>>(Wq, Wk, Wv, Wo, Wfc,
                                               Wq1, Wk1, Wv1, Wo1, Wfc1);
    cudaEventRecord(eW3, s1);

    // L2 (main): zero Zi
    zero_f<<<MTOK / 256, 256>>>(Zi);

    // main waits for weights before projections
    cudaStreamWaitEvent(0, eW3, 0);

    // L3 (main): Q = qf @ Wq
    gemm_nt<4><<<dim3(HIDDEN/128, MTOK/128, 1), blk, GSMEM>>>(
        qfh, Wq1, Qh, EMBED, EMBED, EMBED, HIDDEN, 0, 0, 0, nullptr, nullptr, 0);
    // L4 (main): K = kv @ Wk
    gemm_nt<4><<<dim3(HIDDEN/128, MTOK/128, 1), blk, GSMEM>>>(
        kvh, Wk1, Kh, EMBED, EMBED, EMBED, HIDDEN, 0, 0, 0, nullptr, nullptr, 0);

    // L5 (s1): VT projection, overlapped with Q/K/QK on main
    cudaStreamWaitEvent(s1, eConv, 0);   // needs kvh (w3tr already ordered on s1)
    gemm_nt<4><<<dim3(MTOK/128, HIDDEN/128, 1), blk, GSMEM, s1>>>(
        Wv1, kvh, VT, EMBED, EMBED, EMBED, MTOK, 0, 0, 0, nullptr, nullptr, 0);
    cudaEventRecord(eVT, s1);

    // L6 (main, profiled): S = exp2(QK^T * escale2), Zi += row sums
    qk_f16<<<dim3(SKV/128, SQ/128, NB), blk, GSMEM>>>(Qh, Kh, S, Zi, escale2);

    // join: PV needs VT
    cudaStreamWaitEvent(0, eVT, 0);

    // L7 (main): ctx = (S @ V) / Zi per batch
    gemm_nt<5><<<dim3(HIDDEN/128, SQ/128, NB), blk, GSMEM>>>(
        S, VT, Ch, SKV, SKV, MTOK, HIDDEN,
        (long long)SQ * SKV, (long long)SQ, (long long)SQ * HIDDEN,
        Zi, nullptr, SQ);
    // L8 (main): O1 = ctx @ Wo + bo + q_feat -> fp16
    gemm_nt<3><<<dim3(EMBED/128, MTOK/128, 1), blk, GSMEM>>>(
        Ch, Wo1, O1h, HIDDEN, HIDDEN, HIDDEN, EMBED, 0, 0, 0, bo, q_feat, 0);
    // L9 (main): O2 = O1 @ Wfc -> fp32
    gemm_nt<0><<<dim3(EMBED/128, MTOK/128, 1), blk, GSMEM>>>(
        O1h, Wfc1, O2, EMBED, EMBED, EMBED, EMBED, 0, 0, 0, nullptr, nullptr, 0);
    // L10 (main): layernorm -> out
    layernorm_kernel<<<MTOK, 256>>>(O2, gamma, beta, out);
}

// round 11
// speedup vs baseline: 1.5342x; 1.0791x over previous
#include <cuda_runtime.h>
#include <cuda_fp16.h>
#include <cstdint>
#include <math.h>

#define EMBED  1024
#define HIDDEN 512
#define NB     4
#define SQ     4096
#define SKV    4096
#define MTOK   (NB * SQ)   // 16384
#define HTOK   (MTOK / 2)  // 8192

typedef __half  f16;
typedef __half2 f162;

// ---------------- scratch (static device arrays; no allocations) ----------------
__device__ f16  g_qfh [(size_t)MTOK * EMBED];        // fp16 q_feat
__device__ f16  g_kvh [(size_t)MTOK * EMBED];        // fp16 kv_feat
__device__ f16  g_Qh  [(size_t)MTOK * HIDDEN];       // fp16 Q
__device__ f16  g_Kh  [(size_t)MTOK * HIDDEN];       // fp16 K
__device__ f16  g_VT  [(size_t)HIDDEN * MTOK];       // fp16 V^T [H, tokens]
__device__ f16  g_S   [(size_t)NB * SQ * SKV];       // unnormalized exp-scores
__device__ float g_Zi [MTOK];                        // row sums (atomic)
__device__ f16  g_Ch  [(size_t)MTOK * HIDDEN];       // fp16 ctx
__device__ f16  g_O1h [(size_t)MTOK * EMBED];        // fp16 O1 (ctx@Wo+bo+qf)
__device__ float g_O2 [(size_t)MTOK * EMBED];        // fp32 pre-LN
__device__ f16  g_Wq1 [(size_t)HIDDEN * EMBED];      // fp16 Wq^T
__device__ f16  g_Wk1 [(size_t)HIDDEN * EMBED];
__device__ f16  g_Wv1 [(size_t)HIDDEN * EMBED];
__device__ f16  g_Wo1 [(size_t)EMBED * HIDDEN];      // fp16 Wo^T
__device__ f16  g_Wfc1[(size_t)EMBED * EMBED];       // fp16 Wfc^T

// ================= helpers =================
__device__ __forceinline__ uint32_t smem_u32(const void* p) {
    return (uint32_t)__cvta_generic_to_shared((void*)p);
}
#define SWZ128(o) ((o) ^ (((o) >> 3) & 0x70))

__device__ __forceinline__ void cpa16(uint32_t s, const void* g) {
    asm volatile("cp.async.cg.shared.global [%0], [%1], 16;" :: "r"(s), "l"(g));
}
__device__ __forceinline__ void cpa_commit() {
    asm volatile("cp.async.commit_group;" ::: "memory");
}
template <int N> __device__ __forceinline__ void cpa_wait() {
    asm volatile("cp.async.wait_group %0;" :: "n"(N) : "memory");
}
__device__ __forceinline__ void ldsm_x4(uint32_t a, uint32_t& r0, uint32_t& r1,
                                        uint32_t& r2, uint32_t& r3) {
    asm volatile("ldmatrix.sync.aligned.m8n8.x4.shared.b16 {%0,%1,%2,%3}, [%4];"
                 : "=r"(r0), "=r"(r1), "=r"(r2), "=r"(r3) : "r"(a));
}
__device__ __forceinline__ void mma16816(float* c, const uint32_t* a, const uint32_t* b) {
    asm volatile("mma.sync.aligned.m16n8k16.row.col.f32.f16.f16.f32 "
                 "{%0,%1,%2,%3}, {%4,%5,%6,%7}, {%8,%9}, {%0,%1,%2,%3};"
                 : "+f"(c[0]), "+f"(c[1]), "+f"(c[2]), "+f"(c[3])
                 : "r"(a[0]), "r"(a[1]), "r"(a[2]), "r"(a[3]), "r"(b[0]), "r"(b[1]));
}
// fp16-accumulator HMMA (2 C/D regs of half2)
__device__ __forceinline__ void mma16816h(uint32_t* c, const uint32_t* a, const uint32_t* b) {
    asm volatile("mma.sync.aligned.m16n8k16.row.col.f16.f16.f16.f16 "
                 "{%0,%1}, {%2,%3,%4,%5}, {%6,%7}, {%0,%1};"
                 : "+r"(c[0]), "+r"(c[1])
                 : "r"(a[0]), "r"(a[1]), "r"(a[2]), "r"(a[3]), "r"(b[0]), "r"(b[1]));
}
__device__ __forceinline__ float ex2_mufu(float t) {
    float r;
    asm("ex2.approx.f32 %0, %1;" : "=f"(r) : "f"(t));
    return r;
}

// ================= fp16 NT GEMM (f32 acc) =================
// MODE 0: fp32 store
// MODE 3: +bias[col]+res[row,col] (fp32) -> fp16 store
// MODE 4: fp16 store
// MODE 5: acc / rowsum[z*sAux + r] -> fp16 store
#define STAGE_B 32768
#define GSMEM   (3 * STAGE_B)   // 98304

template <int MODE>
__global__ void __launch_bounds__(256, 2)
gemm_nt(const f16* __restrict__ Ag, const f16* __restrict__ Bg,
        void* __restrict__ Cg, int Kp, int lda, int ldb, int ldc,
        long long sA, long long sB, long long sC,
        const float* __restrict__ aux1, const float* __restrict__ aux2,
        long long sAux)
{
    extern __shared__ char smc[];
    const uint32_t sm0 = smem_u32(smc);
    const int tid  = threadIdx.x;
    const int wid  = tid >> 5;
    const int lane = tid & 31;
    const int wm = wid >> 2;
    const int wn = wid & 3;
    const int m0 = blockIdx.y * 128;
    const int n0 = blockIdx.x * 128;

    Ag += (long long)blockIdx.z * sA;
    Bg += (long long)blockIdx.z * sB;

    const f16* Abase = Ag + (long long)m0 * lda;
    const f16* Bbase = Bg + (long long)n0 * ldb;

    const int crow = tid >> 3;
    const int ccol = tid & 7;

    float acc[4][4][4];
    #pragma unroll
    for (int a = 0; a < 4; a++)
        #pragma unroll
        for (int b = 0; b < 4; b++)
            #pragma unroll
            for (int c = 0; c < 4; c++) acc[a][b][c] = 0.0f;

    const int KT = Kp >> 6;

    auto load_stage = [&](int st, int kt) {
        const uint32_t sa = sm0 + st * STAGE_B;
        const uint32_t sb = sa + 16384;
        const int kofs = kt * 64;
        #pragma unroll
        for (int i = 0; i < 4; i++) {
            const int row = crow + i * 32;
            const uint32_t soff = SWZ128((uint32_t)(row * 128 + ccol * 16));
            cpa16(sa + soff, Abase + (long long)row * lda + kofs + ccol * 8);
            cpa16(sb + soff, Bbase + (long long)row * ldb + kofs + ccol * 8);
        }
    };

    load_stage(0, 0); cpa_commit();
    load_stage(1, 1); cpa_commit();

    int st = 0;
    for (int kt = 0; kt < KT; ++kt) {
        cpa_wait<1>();
        __syncthreads();

        const uint32_t sa = sm0 + st * STAGE_B;
        const uint32_t sb = sa + 16384;

        #pragma unroll
        for (int ks = 0; ks < 4; ks++) {
            uint32_t afr[4][4];
            uint32_t bfr[4][2];
            const int bcol = ks * 32 + ((lane >> 4) << 4);
            #pragma unroll
            for (int mt = 0; mt < 4; mt++) {
                const int row = wm * 64 + mt * 16 + (lane & 15);
                ldsm_x4(sa + SWZ128((uint32_t)(row * 128 + bcol)),
                        afr[mt][0], afr[mt][1], afr[mt][2], afr[mt][3]);
            }
            #pragma unroll
            for (int np = 0; np < 2; np++) {
                const int row = wn * 32 + np * 16 + (lane & 15);
                uint32_t r0, r1, r2, r3;
                ldsm_x4(sb + SWZ128((uint32_t)(row * 128 + bcol)), r0, r1, r2, r3);
                bfr[2*np][0] = r0;   bfr[2*np][1] = r2;
                bfr[2*np+1][0] = r1; bfr[2*np+1][1] = r3;
            }
            #pragma unroll
            for (int mt = 0; mt < 4; mt++)
                #pragma unroll
                for (int nt = 0; nt < 4; nt++)
                    mma16816(acc[mt][nt], afr[mt], bfr[nt]);
        }

        if (kt + 2 < KT) {
            int nst = st + 2; if (nst >= 3) nst -= 3;
            load_stage(nst, kt + 2);
        }
        cpa_commit();
        if (++st == 3) st = 0;
    }

    const float* rs = (MODE == 5) ? (aux1 + (long long)blockIdx.z * sAux) : nullptr;

    #pragma unroll
    for (int mt = 0; mt < 4; mt++) {
        const int r0 = m0 + wm * 64 + mt * 16 + (lane >> 2);
        const int r1 = r0 + 8;
        float rs0 = 1.0f, rs1 = 1.0f;
        if (MODE == 5) { rs0 = 1.0f / rs[r0]; rs1 = 1.0f / rs[r1]; }
        #pragma unroll
        for (int nt = 0; nt < 4; nt++) {
            const int c = n0 + wn * 32 + nt * 8 + (lane & 3) * 2;
            float x0 = acc[mt][nt][0], y0 = acc[mt][nt][1];
            float x1 = acc[mt][nt][2], y1 = acc[mt][nt][3];
            if (MODE == 5) { x0 *= rs0; y0 *= rs0; x1 *= rs1; y1 *= rs1; }
            if (MODE == 3) {
                const float2 bv = *(const float2*)&aux1[c];
                const float2 q0 = *(const float2*)&aux2[(long long)r0 * ldc + c];
                const float2 q1 = *(const float2*)&aux2[(long long)r1 * ldc + c];
                x0 += bv.x + q0.x; y0 += bv.y + q0.y;
                x1 += bv.x + q1.x; y1 += bv.y + q1.y;
            }
            if (MODE == 0) {
                float* Cf = (float*)Cg + (long long)blockIdx.z * sC;
                *(float2*)&Cf[(long long)r0 * ldc + c] = make_float2(x0, y0);
                *(float2*)&Cf[(long long)r1 * ldc + c] = make_float2(x1, y1);
            } else {
                f16* Cb = (f16*)Cg + (long long)blockIdx.z * sC;
                *(f162*)&Cb[(long long)r0 * ldc + c] = __floats2half2_rn(x0, y0);
                *(f162*)&Cb[(long long)r1 * ldc + c] = __floats2half2_rn(x1, y1);
            }
        }
    }
}

// ================= QK^T (fp16 acc) + fused exp2 + atomic row sums =================
__global__ void __launch_bounds__(256, 2)
qk_f16(const f16* __restrict__ Qg, const f16* __restrict__ Kg,
       f16* __restrict__ Sg, float* __restrict__ Zi, float escale2)
{
    extern __shared__ char smc[];
    const uint32_t sm0 = smem_u32(smc);
    const int tid  = threadIdx.x;
    const int wid  = tid >> 5;
    const int lane = tid & 31;
    const int wm = wid >> 2;
    const int wn = wid & 3;
    const int m0 = blockIdx.y * 128;
    const int n0 = blockIdx.x * 128;
    const int z  = blockIdx.z;

    const f16* Abase = Qg + (long long)(z * SQ + m0) * HIDDEN;
    const f16* Bbase = Kg + (long long)(z * SKV + n0) * HIDDEN;

    const int crow = tid >> 3;
    const int ccol = tid & 7;

    uint32_t hacc[4][4][2];
    #pragma unroll
    for (int a = 0; a < 4; a++)
        #pragma unroll
        for (int b = 0; b < 4; b++) { hacc[a][b][0] = 0u; hacc[a][b][1] = 0u; }

    const int KT = HIDDEN >> 6;   // 8

    auto load_stage = [&](int st, int kt) {
        const uint32_t sa = sm0 + st * STAGE_B;
        const uint32_t sb = sa + 16384;
        const int kofs = kt * 64;
        #pragma unroll
        for (int i = 0; i < 4; i++) {
            const int row = crow + i * 32;
            const uint32_t soff = SWZ128((uint32_t)(row * 128 + ccol * 16));
            cpa16(sa + soff, Abase + (long long)row * HIDDEN + kofs + ccol * 8);
            cpa16(sb + soff, Bbase + (long long)row * HIDDEN + kofs + ccol * 8);
        }
    };

    load_stage(0, 0); cpa_commit();
    load_stage(1, 1); cpa_commit();

    int st = 0;
    for (int kt = 0; kt < KT; ++kt) {
        cpa_wait<1>();
        __syncthreads();

        const uint32_t sa = sm0 + st * STAGE_B;
        const uint32_t sb = sa + 16384;

        #pragma unroll
        for (int ks = 0; ks < 4; ks++) {
            uint32_t afr[4][4];
            uint32_t bfr[4][2];
            const int bcol = ks * 32 + ((lane >> 4) << 4);
            #pragma unroll
            for (int mt = 0; mt < 4; mt++) {
                const int row = wm * 64 + mt * 16 + (lane & 15);
                ldsm_x4(sa + SWZ128((uint32_t)(row * 128 + bcol)),
                        afr[mt][0], afr[mt][1], afr[mt][2], afr[mt][3]);
            }
            #pragma unroll
            for (int np = 0; np < 2; np++) {
                const int row = wn * 32 + np * 16 + (lane & 15);
                uint32_t r0, r1, r2, r3;
                ldsm_x4(sb + SWZ128((uint32_t)(row * 128 + bcol)), r0, r1, r2, r3);
                bfr[2*np][0] = r0;   bfr[2*np][1] = r2;
                bfr[2*np+1][0] = r1; bfr[2*np+1][1] = r3;
            }
            #pragma unroll
            for (int mt = 0; mt < 4; mt++)
                #pragma unroll
                for (int nt = 0; nt < 4; nt++)
                    mma16816h(hacc[mt][nt], afr[mt], bfr[nt]);
        }

        if (kt + 2 < KT) {
            int nst = st + 2; if (nst >= 3) nst -= 3;
            load_stage(nst, kt + 2);
        }
        cpa_commit();
        if (++st == 3) st = 0;
    }

    // epilogue: exp2(score * escale2) -> fp16 store + quad-reduced atomic row sums
    f16* Srow = Sg + (long long)z * SQ * SKV;
    float* Ziz = Zi + z * SQ;

    #pragma unroll
    for (int mt = 0; mt < 4; mt++) {
        const int r0 = m0 + wm * 64 + mt * 16 + (lane >> 2);
        const int r1 = r0 + 8;
        float rsum0 = 0.0f, rsum1 = 0.0f;
        #pragma unroll
        for (int nt = 0; nt < 4; nt++) {
            const int c = n0 + wn * 32 + nt * 8 + (lane & 3) * 2;
            const float2 v0 = __half22float2(*(f162*)&hacc[mt][nt][0]);
            const float2 v1 = __half22float2(*(f162*)&hacc[mt][nt][1]);
            float x0 = ex2_mufu(v0.x * escale2);
            float y0 = ex2_mufu(v0.y * escale2);
            float x1 = ex2_mufu(v1.x * escale2);
            float y1 = ex2_mufu(v1.y * escale2);
            rsum0 += x0 + y0;
            rsum1 += x1 + y1;
            *(f162*)&Srow[(long long)r0 * SKV + c] = __floats2half2_rn(x0, y0);
            *(f162*)&Srow[(long long)r1 * SKV + c] = __floats2half2_rn(x1, y1);
        }
        rsum0 += __shfl_xor_sync(0xFFFFFFFFu, rsum0, 1);
        rsum0 += __shfl_xor_sync(0xFFFFFFFFu, rsum0, 2);
        rsum1 += __shfl_xor_sync(0xFFFFFFFFu, rsum1, 1);
        rsum1 += __shfl_xor_sync(0xFFFFFFFFu, rsum1, 2);
        if ((lane & 3) == 0) {
            atomicAdd(&Ziz[r0], rsum0);
            atomicAdd(&Ziz[r1], rsum1);
        }
    }
}

// ============ zero fp32 buffer ============
__global__ void zero_f(float* __restrict__ p)
{
    p[blockIdx.x * 256 + threadIdx.x] = 0.0f;
}

// ============ fp32 -> fp16 convert; blockIdx.y selects tensor ============
__global__ void conv_hi2(const float* __restrict__ X0, const float* __restrict__ X1,
                         f16* __restrict__ Y0, f16* __restrict__ Y1)
{
    const float* X = blockIdx.y ? X1 : X0;
    f16*         Y = blockIdx.y ? Y1 : Y0;
    const long long i4 = (long long)blockIdx.x * blockDim.x + threadIdx.x;
    float4 v = ((const float4*)X)[i4];
    ((f162*)Y)[i4 * 2]     = __floats2half2_rn(v.x, v.y);
    ((f162*)Y)[i4 * 2 + 1] = __floats2half2_rn(v.z, v.w);
}

// ============ all-weights transpose + fp16: z selects the tensor ============
__global__ void w3tr_all(const float* __restrict__ Wq, const float* __restrict__ Wk,
                         const float* __restrict__ Wv, const float* __restrict__ Wo,
                         const float* __restrict__ Wfc,
                         f16* __restrict__ Oq, f16* __restrict__ Ok,
                         f16* __restrict__ Ov, f16* __restrict__ Oo,
                         f16* __restrict__ Ofc)
{
    const int z = blockIdx.z;
    const float* In;
    f16* Out;
    int R, C;
    if (z == 0)      { In = Wq;  Out = Oq;  R = 1024; C = 512; }
    else if (z == 1) { In = Wk;  Out = Ok;  R = 1024; C = 512; }
    else if (z == 2) { In = Wv;  Out = Ov;  R = 1024; C = 512; }
    else if (z == 3) { In = Wo;  Out = Oo;  R = 512;  C = 1024; }
    else             { In = Wfc; Out = Ofc; R = 1024; C = 1024; }

    const int bx = blockIdx.x * 32;   // C
    const int by = blockIdx.y * 32;   // R
    if (bx >= C || by >= R) return;

    __shared__ float t[32][33];
    const int tx = threadIdx.x, ty = threadIdx.y;
    #pragma unroll
    for (int i = ty; i < 32; i += 8)
        t[i][tx] = In[(long long)(by + i) * C + bx + tx];
    __syncthreads();
    #pragma unroll
    for (int i = ty; i < 32; i += 8)
        Out[(long long)(bx + i) * R + by + tx] = __float2half_rn(t[tx][i]);
}

// ================= reductions =================
__device__ __forceinline__ float blockReduceSum(float v, float* sh)
{
    const int t = threadIdx.x;
    #pragma unroll
    for (int o = 16; o; o >>= 1) v += __shfl_xor_sync(0xFFFFFFFFu, v, o);
    if ((t & 31) == 0) sh[t >> 5] = v;
    __syncthreads();
    if (t < 32) {
        float r = (t < 8) ? sh[t] : 0.0f;
        #pragma unroll
        for (int o = 4; o; o >>= 1) r += __shfl_xor_sync(0xFFFFFFFFu, r, o);
        if (t == 0) sh[0] = r;
    }
    __syncthreads();
    float r = sh[0];
    __syncthreads();
    return r;
}

// ================= layernorm =================
__global__ void layernorm_kernel(const float* __restrict__ X,
                                 const float* __restrict__ gamma,
                                 const float* __restrict__ beta,
                                 float* __restrict__ Y)
{
    const float* x = X + (long long)blockIdx.x * EMBED;
    float*       y = Y + (long long)blockIdx.x * EMBED;
    const int t = threadIdx.x;
    __shared__ float sh[32];

    float4 v = *(const float4*)&x[t * 4];
    float s = v.x + v.y + v.z + v.w;
    s = blockReduceSum(s, sh);
    const float mu = s * (1.0f / EMBED);

    float dx = v.x - mu, dy = v.y - mu, dz = v.z - mu, dw = v.w - mu;
    float sq = dx * dx + dy * dy + dz * dz + dw * dw;
    sq = blockReduceSum(sq, sh);
    const float rstd = rsqrtf(sq * (1.0f / EMBED) + 1e-5f);

    float4 g = *(const float4*)&gamma[t * 4];
    float4 b = *(const float4*)&beta[t * 4];
    float4 o;
    o.x = dx * rstd * g.x + b.x;
    o.y = dy * rstd * g.y + b.y;
    o.z = dz * rstd * g.z + b.z;
    o.w = dw * rstd * g.w + b.w;
    *(float4*)&y[t * 4] = o;
}

// ================= launch =================
extern "C" void kernel_launch(void* const* d_in, const int* in_sizes, int n_in,
                              void* d_out, int out_size)
{
    const float* q_feat = (const float*)d_in[0];
    const float* kv     = (const float*)d_in[1];
    const float* Wq     = (const float*)d_in[2];
    const float* Wk     = (const float*)d_in[3];
    const float* Wv     = (const float*)d_in[4];
    const float* Wo     = (const float*)d_in[5];
    const float* bo     = (const float*)d_in[6];
    const float* Wfc    = (const float*)d_in[7];
    const float* gamma  = (const float*)d_in[8];
    const float* beta   = (const float*)d_in[9];
    float* out = (float*)d_out;

    f16 *qfh, *kvh, *Qh, *Kh, *VT, *S, *Ch, *O1h, *Wq1, *Wk1, *Wv1, *Wo1, *Wfc1;
    float *Zi, *O2;
    cudaGetSymbolAddress((void**)&qfh,  g_qfh);
    cudaGetSymbolAddress((void**)&kvh,  g_kvh);
    cudaGetSymbolAddress((void**)&Qh,   g_Qh);
    cudaGetSymbolAddress((void**)&Kh,   g_Kh);
    cudaGetSymbolAddress((void**)&VT,   g_VT);
    cudaGetSymbolAddress((void**)&S,    g_S);
    cudaGetSymbolAddress((void**)&Zi,   g_Zi);
    cudaGetSymbolAddress((void**)&Ch,   g_Ch);
    cudaGetSymbolAddress((void**)&O1h,  g_O1h);
    cudaGetSymbolAddress((void**)&O2,   g_O2);
    cudaGetSymbolAddress((void**)&Wq1,  g_Wq1);
    cudaGetSymbolAddress((void**)&Wk1,  g_Wk1);
    cudaGetSymbolAddress((void**)&Wv1,  g_Wv1);
    cudaGetSymbolAddress((void**)&Wo1,  g_Wo1);
    cudaGetSymbolAddress((void**)&Wfc1, g_Wfc1);

    cudaFuncSetAttribute(gemm_nt<0>, cudaFuncAttributeMaxDynamicSharedMemorySize, GSMEM);
    cudaFuncSetAttribute(gemm_nt<3>, cudaFuncAttributeMaxDynamicSharedMemorySize, GSMEM);
    cudaFuncSetAttribute(gemm_nt<4>, cudaFuncAttributeMaxDynamicSharedMemorySize, GSMEM);
    cudaFuncSetAttribute(gemm_nt<5>, cudaFuncAttributeMaxDynamicSharedMemorySize, GSMEM);
    cudaFuncSetAttribute(qk_f16, cudaFuncAttributeMaxDynamicSharedMemorySize, GSMEM);

    const dim3 blk(256);
    const dim3 tblk(32, 8);
    const float escale2 = 0.044194173824159216f * 1.4426950408889634f;

    // side stream + events (fresh per call; no device allocations)
    cudaStream_t s1;
    cudaStreamCreate(&s1);
    cudaEvent_t eFork, eConv, eW3, eKp, eVT, eQK, eEnd;
    cudaEventCreateWithFlags(&eFork, cudaEventDisableTiming);
    cudaEventCreateWithFlags(&eConv, cudaEventDisableTiming);
    cudaEventCreateWithFlags(&eW3,   cudaEventDisableTiming);
    cudaEventCreateWithFlags(&eKp,   cudaEventDisableTiming);
    cudaEventCreateWithFlags(&eVT,   cudaEventDisableTiming);
    cudaEventCreateWithFlags(&eQK,   cudaEventDisableTiming);
    cudaEventCreateWithFlags(&eEnd,  cudaEventDisableTiming);

    // fork
    cudaEventRecord(eFork, 0);
    cudaStreamWaitEvent(s1, eFork, 0);

    // L0 (main): fp32 -> fp16 converts
    conv_hi2<<<dim3(MTOK * EMBED / 4 / 256, 2), 256>>>(q_feat, kv, qfh, kvh);
    cudaEventRecord(eConv, 0);

    // L1 (s1): all 5 weight transposes
    w3tr_all<<<dim3(32, 32, 5), tblk, 0, s1>>>(Wq, Wk, Wv, Wo, Wfc,
                                               Wq1, Wk1, Wv1, Wo1, Wfc1);
    cudaEventRecord(eW3, s1);

    // L2 (main): zero Zi
    zero_f<<<MTOK / 256, 256>>>(Zi);

    // main waits weights; s1 waits conv (for kvh)
    cudaStreamWaitEvent(0, eW3, 0);
    cudaStreamWaitEvent(s1, eConv, 0);

    // L3 (main): Q = qf @ Wq
    gemm_nt<4><<<dim3(HIDDEN/128, MTOK/128, 1), blk, GSMEM>>>(
        qfh, Wq1, Qh, EMBED, EMBED, EMBED, HIDDEN, 0, 0, 0, nullptr, nullptr, 0);
    // L4 (s1): K = kv @ Wk (concurrent with Qproj)
    gemm_nt<4><<<dim3(HIDDEN/128, MTOK/128, 1), blk, GSMEM, s1>>>(
        kvh, Wk1, Kh, EMBED, EMBED, EMBED, HIDDEN, 0, 0, 0, nullptr, nullptr, 0);
    cudaEventRecord(eKp, s1);

    // main needs Kh before QK
    cudaStreamWaitEvent(0, eKp, 0);

    // L5 (main, profiled): S = exp2(QK^T * escale2), Zi += row sums
    qk_f16<<<dim3(SKV/128, SQ/128, NB), blk, GSMEM>>>(Qh, Kh, S, Zi, escale2);
    cudaEventRecord(eQK, 0);

    // L6 (s1): VT projection (overlaps QK on main)
    gemm_nt<4><<<dim3(MTOK/128, HIDDEN/128, 1), blk, GSMEM, s1>>>(
        Wv1, kvh, VT, EMBED, EMBED, EMBED, MTOK, 0, 0, 0, nullptr, nullptr, 0);
    cudaEventRecord(eVT, s1);

    // join for PV halves
    cudaStreamWaitEvent(0, eVT, 0);   // main: PV_A needs VT
    cudaStreamWaitEvent(s1, eQK, 0);  // s1: PV_B needs S,Zi

    // ---- half A (batches 0,1 / tokens 0..8191) on main ----
    // L7: PV_A = (S @ V)/Zi for z=0,1
    gemm_nt<5><<<dim3(HIDDEN/128, SQ/128, 2), blk, GSMEM>>>(
        S, VT, Ch, SKV, SKV, MTOK, HIDDEN,
        (long long)SQ * SKV, (long long)SQ, (long long)SQ * HIDDEN,
        Zi, nullptr, SQ);
    // ---- half B (batches 2,3 / tokens 8192..16383) on s1 ----
    // L8: PV_B
    gemm_nt<5><<<dim3(HIDDEN/128, SQ/128, 2), blk, GSMEM, s1>>>(
        S + 2LL * SQ * SKV, VT + 2LL * SQ, Ch + 2LL * SQ * HIDDEN,
        SKV, SKV, MTOK, HIDDEN,
        (long long)SQ * SKV, (long long)SQ, (long long)SQ * HIDDEN,
        Zi + 2LL * SQ, nullptr, SQ);

    // L9 (main): O1_A = ctx @ Wo + bo + q_feat (tokens 0..8191)
    gemm_nt<3><<<dim3(EMBED/128, HTOK/128, 1), blk, GSMEM>>>(
        Ch, Wo1, O1h, HIDDEN, HIDDEN, HIDDEN, EMBED, 0, 0, 0, bo, q_feat, 0);
    // L10 (s1): O1_B (tokens 8192..16383)
    gemm_nt<3><<<dim3(EMBED/128, HTOK/128, 1), blk, GSMEM, s1>>>(
        Ch + (long long)HTOK * HIDDEN, Wo1, O1h + (long long)HTOK * EMBED,
        HIDDEN, HIDDEN, HIDDEN, EMBED, 0, 0, 0,
        bo, q_feat + (long long)HTOK * EMBED, 0);

    // L11 (main): Wfc_A
    gemm_nt<0><<<dim3(EMBED/128, HTOK/128, 1), blk, GSMEM>>>(
        O1h, Wfc1, O2, EMBED, EMBED, EMBED, EMBED, 0, 0, 0, nullptr, nullptr, 0);
    // L12 (s1): Wfc_B
    gemm_nt<0><<<dim3(EMBED/128, HTOK/128, 1), blk, GSMEM, s1>>>(
        O1h + (long long)HTOK * EMBED, Wfc1, O2 + (long long)HTOK * EMBED,
        EMBED, EMBED, EMBED, EMBED, 0, 0, 0, nullptr, nullptr, 0);

    // L13 (main): LN_A
    layernorm_kernel<<<HTOK, 256>>>(O2, gamma, beta, out);
    // L14 (s1): LN_B
    layernorm_kernel<<<HTOK, 256, 0, s1>>>(
        O2 + (long long)HTOK * EMBED, gamma, beta, out + (long long)HTOK * EMBED);
    cudaEventRecord(eEnd, s1);

    // join s1 back into main (required for capture; orders completion)
    cudaStreamWaitEvent(0, eEnd, 0);
}